// round 10
// baseline (speedup 1.0000x reference)
#include <cuda_runtime.h>
#include <cuda_bf16.h>
#include <cstdint>
#include <stdint.h>
#include <math.h>

// ---------------------------------------------------------------------------
// Problem constants
// ---------------------------------------------------------------------------
#define Bq   8
#define Lq   4096
#define Dq   256
#define Nslot 512
#define Hq   8
#define NTOK (Bq*Lq)       // 32768
#define NSROW (Bq*Nslot)   // 4096

// ---------------------------------------------------------------------------
// Device scratch. "sp" buffers are split bf16 planes: hi at base, lo at +PL.
// ---------------------------------------------------------------------------
__device__ __nv_bfloat16 g_Xsp   [2 * NTOK * 256];
__device__ __nv_bfloat16 g_Ssp   [2 * NSROW * 256];
__device__ __nv_bfloat16 g_H1sp  [2 * NTOK * 512];
__device__ __nv_bfloat16 g_qkvsp [2 * NSROW * 768];
__device__ __nv_bfloat16 g_attnsp[2 * NSROW * 256];
__device__ __nv_bfloat16 g_catsp [2 * NSROW * 512];
__device__ __nv_bfloat16 g_Usp   [2 * NSROW * 512];
// weights, transposed to [N][K] hi/lo planes
__device__ __nv_bfloat16 g_Wm1t [2 * 512 * 256];
__device__ __nv_bfloat16 g_Wm2t [2 * 256 * 512];
__device__ __nv_bfloat16 g_Wgt1t[2 * 256 * 256];
__device__ __nv_bfloat16 g_Wqkvt[2 * 768 * 256];
__device__ __nv_bfloat16 g_Wot  [2 * 256 * 256];
__device__ __nv_bfloat16 g_Wu1t [2 * 512 * 512];
__device__ __nv_bfloat16 g_Wu2t [2 * 256 * 512];
// fp32 intermediates
__device__ float g_msg  [NTOK * 256];
__device__ float g_T1   [NTOK * 256];
__device__ float g_gate [NTOK];
__device__ int   g_idx  [NTOK];
__device__ float g_oproj[NSROW * 256];
__device__ float g_S1   [NSROW * 256];
__device__ float g_S2   [NSROW * 256];

// ---------------------------------------------------------------------------
// Helpers
// ---------------------------------------------------------------------------
__device__ __forceinline__ float gelu_exact(float x) {
    return 0.5f * x * (1.0f + erff(x * 0.70710678118654752f));
}

__device__ __forceinline__ void ldsm4(uint32_t addr, uint32_t& r0, uint32_t& r1,
                                      uint32_t& r2, uint32_t& r3) {
    asm volatile("ldmatrix.sync.aligned.m8n8.x4.shared.b16 {%0,%1,%2,%3}, [%4];"
                 : "=r"(r0), "=r"(r1), "=r"(r2), "=r"(r3) : "r"(addr));
}

__device__ __forceinline__ void mma_bf16(float* c, const uint32_t* a,
                                         uint32_t b0, uint32_t b1) {
    asm volatile(
        "mma.sync.aligned.m16n8k16.row.col.f32.bf16.bf16.f32 "
        "{%0,%1,%2,%3}, {%4,%5,%6,%7}, {%8,%9}, {%0,%1,%2,%3};\n"
        : "+f"(c[0]), "+f"(c[1]), "+f"(c[2]), "+f"(c[3])
        : "r"(a[0]), "r"(a[1]), "r"(a[2]), "r"(a[3]), "r"(b0), "r"(b1));
}

__device__ __forceinline__ void hilo2(float a, float b, uint32_t& h, uint32_t& l) {
    __nv_bfloat16 ha = __float2bfloat16(a), hb = __float2bfloat16(b);
    __nv_bfloat162 hh; hh.x = ha; hh.y = hb;
    __nv_bfloat162 ll;
    ll.x = __float2bfloat16(a - __bfloat162float(ha));
    ll.y = __float2bfloat16(b - __bfloat162float(hb));
    h = *(uint32_t*)&hh; l = *(uint32_t*)&ll;
}

__device__ __forceinline__ void cpasync16(uint32_t dst, const void* src) {
    asm volatile("cp.async.cg.shared.global [%0], [%1], 16;"
                 :: "r"(dst), "l"(src));
}
__device__ __forceinline__ void cpcommit() {
    asm volatile("cp.async.commit_group;" ::: "memory");
}

// ---------------------------------------------------------------------------
// Elementwise fp32 -> hi/lo bf16 planes.
// ---------------------------------------------------------------------------
__global__ void __launch_bounds__(256)
fsplit(const float* __restrict__ s, __nv_bfloat16* __restrict__ d, size_t n)
{
    size_t i = ((size_t)blockIdx.x * 256 + threadIdx.x) * 8;
    if (i >= n) return;
    float4 a = *(const float4*)(s + i);
    float4 b = *(const float4*)(s + i + 4);
    float f[8] = {a.x, a.y, a.z, a.w, b.x, b.y, b.z, b.w};
    union { __nv_bfloat16 bb[8]; uint4 u; } hu, lu;
#pragma unroll
    for (int j = 0; j < 8; j++) {
        __nv_bfloat16 hh = __float2bfloat16(f[j]);
        hu.bb[j] = hh;
        lu.bb[j] = __float2bfloat16(f[j] - __bfloat162float(hh));
    }
    *(uint4*)(d + i)     = hu.u;
    *(uint4*)(d + n + i) = lu.u;
}

// ---------------------------------------------------------------------------
// Weight transpose+split: W[K][N] fp32 -> D[N][K] hi/lo bf16 planes.
// ---------------------------------------------------------------------------
__global__ void __launch_bounds__(256)
wsplit(const float* __restrict__ W, __nv_bfloat16* __restrict__ D, int K, int N)
{
    __shared__ float tile[32][33];
    const int n0 = blockIdx.x * 32, k0 = blockIdx.y * 32;
    for (int i = threadIdx.y; i < 32; i += 8)
        tile[i][threadIdx.x] = W[(size_t)(k0 + i) * N + n0 + threadIdx.x];
    __syncthreads();
    const size_t PL = (size_t)K * N;
    for (int i = threadIdx.y; i < 32; i += 8) {
        float v = tile[threadIdx.x][i];
        __nv_bfloat16 hh = __float2bfloat16(v);
        size_t o = (size_t)(n0 + i) * K + k0 + threadIdx.x;
        D[o]      = hh;
        D[PL + o] = __float2bfloat16(v - __bfloat162float(hh));
    }
}

// ---------------------------------------------------------------------------
// bf16x3 split GEMM v3: 256 threads (8 warps, warp tile 32x64), CTA tile
// 128x128, 2-stage cp.async pipeline, 2 CTAs/SM.
// A: [M][K] hi/lo planes; B: [N][K] hi/lo planes.
// Stage (40960B): Ah@0 Al@10240 Bh@20480 Bl@30720 (row stride 80B).
// ---------------------------------------------------------------------------
#define STRD 40
#define TILE_E (128 * STRD)
#define STG_E  (4 * TILE_E)
#define GEMM_SMEM (2 * STG_E * 2)   // 81920 bytes

__device__ __forceinline__ void gload(
    uint32_t st, const __nv_bfloat16* Ah, const __nv_bfloat16* Al,
    const __nv_bfloat16* Bh, const __nv_bfloat16* Bl, int Kd, int k0, int tid)
{
    const int r  = tid >> 1;
    const int c0 = (tid & 1) * 2;
#pragma unroll
    for (int i = 0; i < 2; i++) {
        const int c = c0 + i;
        const uint32_t d = st + (uint32_t)(r * 80 + c * 16);
        const size_t g = (size_t)r * Kd + k0 + c * 8;
        cpasync16(d,         Ah + g);
        cpasync16(d + 10240, Al + g);
        cpasync16(d + 20480, Bh + g);
        cpasync16(d + 30720, Bl + g);
    }
}

template<int ACT, int HAS_RES, int OUT_SPLIT>
__global__ void __launch_bounds__(256, 2)
bf3gemm(int M, int Nd, int Kd,
        const __nv_bfloat16* __restrict__ Asp, const __nv_bfloat16* __restrict__ Bsp,
        const float* __restrict__ bias, const float* __restrict__ Res,
        void* __restrict__ Cout)
{
    extern __shared__ char smem[];
    const uint32_t sb = (uint32_t)__cvta_generic_to_shared(smem);

    const int tid = threadIdx.x, lane = tid & 31, warp = tid >> 5;
    const int wm = (warp & 3) * 32;     // warp row base (4 row-warps)
    const int wn = (warp >> 2) * 64;    // warp col base (2 col-warps)
    const int br = blockIdx.y, bc = blockIdx.x;

    const size_t APL = (size_t)M * Kd, BPL = (size_t)Nd * Kd;
    const __nv_bfloat16* Ahp = Asp + (size_t)(br * 128) * Kd;
    const __nv_bfloat16* Alp = Ahp + APL;
    const __nv_bfloat16* Bhp = Bsp + (size_t)(bc * 128) * Kd;
    const __nv_bfloat16* Blp = Bhp + BPL;

    float acc[2][8][4];
#pragma unroll
    for (int i = 0; i < 2; i++)
#pragma unroll
        for (int j = 0; j < 8; j++)
#pragma unroll
            for (int q = 0; q < 4; q++) acc[i][j][q] = 0.f;

    const int lr = lane & 15;
    const uint32_t lkB = (uint32_t)(lane >> 4) * 16;
    const uint32_t aA = sb + (uint32_t)(wm + lr) * 80 + lkB;           // A hi (+10240 lo)
    const uint32_t aB = sb + 20480 + (uint32_t)(wn + lr) * 80 + lkB;   // B hi (+10240 lo)
    const uint32_t STGB = 40960;
    const uint32_t HOP  = 16 * 80;   // 16-row hop = 1280B

    const int nIter = Kd >> 5;

    // prologue: stages 0,1
    gload(sb,        Ahp, Alp, Bhp, Blp, Kd, 0,  tid); cpcommit();
    gload(sb + STGB, Ahp, Alp, Bhp, Blp, Kd, 32, tid); cpcommit();

    for (int it = 0; it < nIter; it++) {
        asm volatile("cp.async.wait_group 1;" ::: "memory");
        __syncthreads();

        const uint32_t po = (uint32_t)(it & 1) * STGB;
#pragma unroll
        for (int ks = 0; ks < 2; ks++) {
            const uint32_t ko = po + ks * 32;
            uint32_t fah[2][4], fal[2][4];
#pragma unroll
            for (int i = 0; i < 2; i++) {
                ldsm4(aA + i * HOP + ko,         fah[i][0], fah[i][1], fah[i][2], fah[i][3]);
                ldsm4(aA + 10240 + i * HOP + ko, fal[i][0], fal[i][1], fal[i][2], fal[i][3]);
            }
#pragma unroll
            for (int j2 = 0; j2 < 2; j2++) {
                uint32_t fbh[2][4], fbl[2][4];
#pragma unroll
                for (int g2 = 0; g2 < 2; g2++) {
                    const uint32_t bo = (uint32_t)(j2 * 2 + g2) * HOP + ko;
                    ldsm4(aB + bo,         fbh[g2][0], fbh[g2][1], fbh[g2][2], fbh[g2][3]);
                    ldsm4(aB + 10240 + bo, fbl[g2][0], fbl[g2][1], fbl[g2][2], fbl[g2][3]);
                }
#pragma unroll
                for (int i = 0; i < 2; i++)
#pragma unroll
                    for (int g2 = 0; g2 < 2; g2++)
#pragma unroll
                        for (int od = 0; od < 2; od++) {
                            const int j8 = j2 * 4 + g2 * 2 + od;
                            mma_bf16(acc[i][j8], fah[i], fbh[g2][od], fbh[g2][od + 2]);
                            mma_bf16(acc[i][j8], fah[i], fbl[g2][od], fbl[g2][od + 2]);
                            mma_bf16(acc[i][j8], fal[i], fbh[g2][od], fbh[g2][od + 2]);
                        }
            }
        }
        __syncthreads();

        if (it + 2 < nIter)
            gload(sb + po, Ahp, Alp, Bhp, Blp, Kd, (it + 2) * 32, tid);
        cpcommit();
    }

    // epilogue
    const int er = lane >> 2;
    const int ec = (lane & 3) * 2;
#pragma unroll
    for (int i = 0; i < 2; i++) {
        const int row0 = br * 128 + wm + i * 16 + er;
#pragma unroll
        for (int j8 = 0; j8 < 8; j8++) {
            const int col = bc * 128 + wn + j8 * 8 + ec;
            const float b0 = bias[col], b1 = bias[col + 1];
            float v0 = acc[i][j8][0] + b0, v1 = acc[i][j8][1] + b1;
            float v2 = acc[i][j8][2] + b0, v3 = acc[i][j8][3] + b1;
            if (ACT) { v0 = gelu_exact(v0); v1 = gelu_exact(v1);
                       v2 = gelu_exact(v2); v3 = gelu_exact(v3); }
            const size_t o0 = (size_t)row0 * Nd + col;
            const size_t o1 = (size_t)(row0 + 8) * Nd + col;
            if (HAS_RES) {
                v0 += Res[o0]; v1 += Res[o0 + 1];
                v2 += Res[o1]; v3 += Res[o1 + 1];
            }
            if (OUT_SPLIT) {
                __nv_bfloat16* Ch = (__nv_bfloat16*)Cout;
                __nv_bfloat16* Cl = Ch + (size_t)M * Nd;
                uint32_t h0, l0, h1, l1;
                hilo2(v0, v1, h0, l0);
                hilo2(v2, v3, h1, l1);
                *(uint32_t*)(Ch + o0) = h0; *(uint32_t*)(Cl + o0) = l0;
                *(uint32_t*)(Ch + o1) = h1; *(uint32_t*)(Cl + o1) = l1;
            } else {
                float* C = (float*)Cout;
                float2 w0; w0.x = v0; w0.y = v1;
                float2 w1; w1.x = v2; w1.y = v3;
                *(float2*)&C[o0] = w0;
                *(float2*)&C[o1] = w1;
            }
        }
    }
}

// ---------------------------------------------------------------------------
// Routing with smem-cached weights (validated round 5).
// ---------------------------------------------------------------------------
#define ROUTE_SMEM ((256*64 + 256*8 + 32*256) * 4)
__global__ void __launch_bounds__(256)
route_kernel(const float* __restrict__ X, const float* __restrict__ Wg,
             const float* __restrict__ Wk, int* __restrict__ idx)
{
    extern __shared__ float rsm[];
    float* sWg = rsm;
    float* sWk = rsm + 256 * 64;
    float* sX  = rsm + 256 * 64 + 256 * 8;

    const int t = threadIdx.x, lane = t & 31, w = t >> 5;
    const int tok0 = blockIdx.x * 32;

    for (int i = t; i < 256 * 64 / 4; i += 256)
        *(float4*)&sWg[i * 4] = *(const float4*)&Wg[i * 4];
    for (int i = t; i < 256 * 8 / 4; i += 256)
        *(float4*)&sWk[i * 4] = *(const float4*)&Wk[i * 4];
    for (int i = t; i < 32 * 256 / 4; i += 256)
        *(float4*)&sX[i * 4] = *(const float4*)&X[(size_t)tok0 * 256 + i * 4];
    __syncthreads();

    for (int r = 0; r < 4; r++) {
        const int tk = w * 4 + r;
        const float* x = &sX[tk * 256];
        float a0 = 0.f, a1 = 0.f, ak = 0.f;
        const int kl = lane & 7;
#pragma unroll 4
        for (int k = 0; k < 256; k++) {
            const float xv = x[k];
            a0 = fmaf(xv, sWg[k * 64 + lane], a0);
            a1 = fmaf(xv, sWg[k * 64 + lane + 32], a1);
            ak = fmaf(xv, sWk[k * 8 + kl], ak);
        }
        float bv = a0; int bi = lane;
        if (a1 > bv) { bv = a1; bi = lane + 32; }
#pragma unroll
        for (int o = 16; o; o >>= 1) {
            float ov = __shfl_xor_sync(0xffffffffu, bv, o);
            int   oi = __shfl_xor_sync(0xffffffffu, bi, o);
            if (ov > bv || (ov == bv && oi < bi)) { bv = ov; bi = oi; }
        }
        float kv = ak; int ki = kl;
#pragma unroll
        for (int o = 4; o; o >>= 1) {
            float ov = __shfl_xor_sync(0xffffffffu, kv, o);
            int   oi = __shfl_xor_sync(0xffffffffu, ki, o);
            if (ov > kv || (ov == kv && oi < ki)) { kv = ov; ki = oi; }
        }
        if (lane == 0) idx[tok0 + tk] = bi * 8 + ki;
    }
}

// ---------------------------------------------------------------------------
// gate = sigmoid(T1 . Wgt2 + bgt2)
// ---------------------------------------------------------------------------
__global__ void __launch_bounds__(256)
gate_kernel(const float* __restrict__ T1, const float* __restrict__ Wgt2,
            const float* __restrict__ bgt2, float* __restrict__ gate)
{
    const int warp = threadIdx.x >> 5, lane = threadIdx.x & 31;
    const int tok = blockIdx.x * 8 + warp;
    const float* r = T1 + (size_t)tok * 256;
    float s = 0.f;
#pragma unroll
    for (int i = 0; i < 8; i++) s = fmaf(r[lane + 32 * i], Wgt2[lane + 32 * i], s);
#pragma unroll
    for (int o = 16; o; o >>= 1) s += __shfl_xor_sync(0xffffffffu, s, o);
    if (lane == 0) gate[tok] = 1.f / (1.f + expf(-(s + bgt2[0])));
}

// ---------------------------------------------------------------------------
// incoming -> cat planes [:,256:512]. Ballot scan (validated round 4).
// ---------------------------------------------------------------------------
__global__ void __launch_bounds__(256)
gather_kernel(const float* __restrict__ msg, const float* __restrict__ gate,
              const int* __restrict__ idx, __nv_bfloat16* __restrict__ cat)
{
    __shared__ float part[8][256];
    const int t = threadIdx.x, lane = t & 31, w = t >> 5;
    const int b = blockIdx.x >> 9;
    const int n = blockIdx.x & 511;
    const int base0 = b * 4096 + w * 512;

    float acc[8];
#pragma unroll
    for (int e = 0; e < 8; e++) acc[e] = 0.f;

    for (int s = 0; s < 16; s++) {
        const int l = base0 + s * 32 + lane;
        const int iv = idx[l];
        const float gv = gate[l];
        unsigned m = __ballot_sync(0xffffffffu, iv == n);
        while (m) {
            const int j = __ffs(m) - 1;
            m &= m - 1;
            const float g = __shfl_sync(0xffffffffu, gv, j);
            const float* row = msg + (size_t)(base0 + s * 32 + j) * 256;
#pragma unroll
            for (int e = 0; e < 8; e++)
                acc[e] = fmaf(g, row[e * 32 + lane], acc[e]);
        }
    }
#pragma unroll
    for (int e = 0; e < 8; e++) part[w][e * 32 + lane] = acc[e];
    __syncthreads();

    float s = 0.f;
#pragma unroll
    for (int w2 = 0; w2 < 8; w2++) s += part[w2][t];
    const size_t PL = (size_t)gridDim.x * 512;
    const size_t o = (size_t)blockIdx.x * 512 + 256 + t;
    __nv_bfloat16 hh = __float2bfloat16(s);
    cat[o]      = hh;
    cat[PL + o] = __float2bfloat16(s - __bfloat162float(hh));
}

// ---------------------------------------------------------------------------
// Tensor-core flash attention on split qkv planes (validated round 8).
// ---------------------------------------------------------------------------
#define ATTN_SMEM 168960
__global__ void __launch_bounds__(256, 1)
attn_tc(const __nv_bfloat16* __restrict__ qkvsp, __nv_bfloat16* __restrict__ Osp)
{
    extern __shared__ __nv_bfloat16 abuf[];
    __nv_bfloat16* sQh = abuf;
    __nv_bfloat16* sQl = abuf + 5120;
    __nv_bfloat16* sKh = abuf + 10240;
    __nv_bfloat16* sKl = abuf + 30720;
    __nv_bfloat16* sVh = abuf + 51200;
    __nv_bfloat16* sVl = abuf + 67840;

    const int b = blockIdx.x >> 3, h = blockIdx.x & 7;
    const int qc = blockIdx.y;
    const int tid = threadIdx.x, lane = tid & 31, warp = tid >> 5;
    const __nv_bfloat16* gh = qkvsp;
    const __nv_bfloat16* gl = qkvsp + (size_t)NSROW * 768;
    const float scale = 0.17677669529663687f;

    for (int i = tid; i < 128 * 32; i += 256) {
        int q = i >> 5, d = i & 31;
        size_t off = (size_t)(b * 512 + qc * 128 + q) * 768 + h * 32 + d;
        sQh[q * 40 + d] = gh[off];
        sQl[q * 40 + d] = gl[off];
    }
    for (int i = tid; i < 512 * 32; i += 256) {
        int n = i >> 5, d = i & 31;
        size_t offk = (size_t)(b * 512 + n) * 768 + 256 + h * 32 + d;
        size_t offv = offk + 256;
        sKh[n * 40 + d] = gh[offk];
        sKl[n * 40 + d] = gl[offk];
        sVh[d * 520 + n] = gh[offv];
        sVl[d * 520 + n] = gl[offv];
    }
    __syncthreads();

    const int lr = lane & 15;
    const int lkB = (lane >> 4) * 16;

    uint32_t qh[2][4], ql[2][4];
    {
        uint32_t a0 = (uint32_t)__cvta_generic_to_shared(&sQh[(warp * 16 + lr) * 40]) + lkB;
        uint32_t a1 = (uint32_t)__cvta_generic_to_shared(&sQl[(warp * 16 + lr) * 40]) + lkB;
        ldsm4(a0,      qh[0][0], qh[0][1], qh[0][2], qh[0][3]);
        ldsm4(a0 + 32, qh[1][0], qh[1][1], qh[1][2], qh[1][3]);
        ldsm4(a1,      ql[0][0], ql[0][1], ql[0][2], ql[0][3]);
        ldsm4(a1 + 32, ql[1][0], ql[1][1], ql[1][2], ql[1][3]);
    }
    const uint32_t aKh0 = (uint32_t)__cvta_generic_to_shared(&sKh[lr * 40]) + lkB;
    const uint32_t aKl0 = (uint32_t)__cvta_generic_to_shared(&sKl[lr * 40]) + lkB;
    const uint32_t aVh0 = (uint32_t)__cvta_generic_to_shared(&sVh[lr * 520]) + lkB;
    const uint32_t aVl0 = (uint32_t)__cvta_generic_to_shared(&sVl[lr * 520]) + lkB;

    float m0 = -1e30f, m1 = -1e30f, l0 = 0.f, l1 = 0.f;
    float Oa[4][4];
#pragma unroll
    for (int i = 0; i < 4; i++)
#pragma unroll
        for (int j = 0; j < 4; j++) Oa[i][j] = 0.f;

    for (int c = 0; c < 4; c++) {
        float s[16][4];
#pragma unroll
        for (int jn = 0; jn < 16; jn++)
#pragma unroll
            for (int q = 0; q < 4; q++) s[jn][q] = 0.f;

#pragma unroll
        for (int ks = 0; ks < 2; ks++) {
#pragma unroll
            for (int jq = 0; jq < 8; jq++) {
                const uint32_t off = (uint32_t)((c * 128 + jq * 16) * 80) + ks * 32;
                uint32_t kb[4], kl[4];
                ldsm4(aKh0 + off, kb[0], kb[1], kb[2], kb[3]);
                ldsm4(aKl0 + off, kl[0], kl[1], kl[2], kl[3]);
#pragma unroll
                for (int od = 0; od < 2; od++) {
                    const int jn = jq * 2 + od;
                    mma_bf16(s[jn], qh[ks], kb[od], kb[od + 2]);
                    mma_bf16(s[jn], qh[ks], kl[od], kl[od + 2]);
                    mma_bf16(s[jn], ql[ks], kb[od], kb[od + 2]);
                }
            }
        }

#pragma unroll
        for (int jn = 0; jn < 16; jn++) {
            s[jn][0] *= scale; s[jn][1] *= scale;
            s[jn][2] *= scale; s[jn][3] *= scale;
        }

        float cm0 = -1e30f, cm1 = -1e30f;
#pragma unroll
        for (int jn = 0; jn < 16; jn++) {
            cm0 = fmaxf(cm0, fmaxf(s[jn][0], s[jn][1]));
            cm1 = fmaxf(cm1, fmaxf(s[jn][2], s[jn][3]));
        }
        cm0 = fmaxf(cm0, __shfl_xor_sync(0xffffffffu, cm0, 1));
        cm0 = fmaxf(cm0, __shfl_xor_sync(0xffffffffu, cm0, 2));
        cm1 = fmaxf(cm1, __shfl_xor_sync(0xffffffffu, cm1, 1));
        cm1 = fmaxf(cm1, __shfl_xor_sync(0xffffffffu, cm1, 2));
        const float nm0 = fmaxf(m0, cm0), nm1 = fmaxf(m1, cm1);
        const float f0 = __expf(m0 - nm0), f1 = __expf(m1 - nm1);
        m0 = nm0; m1 = nm1;
        float ps0 = 0.f, ps1 = 0.f;
#pragma unroll
        for (int jn = 0; jn < 16; jn++) {
            s[jn][0] = __expf(s[jn][0] - m0);
            s[jn][1] = __expf(s[jn][1] - m0);
            s[jn][2] = __expf(s[jn][2] - m1);
            s[jn][3] = __expf(s[jn][3] - m1);
            ps0 += s[jn][0] + s[jn][1];
            ps1 += s[jn][2] + s[jn][3];
        }
        ps0 += __shfl_xor_sync(0xffffffffu, ps0, 1);
        ps0 += __shfl_xor_sync(0xffffffffu, ps0, 2);
        ps1 += __shfl_xor_sync(0xffffffffu, ps1, 1);
        ps1 += __shfl_xor_sync(0xffffffffu, ps1, 2);
        l0 = l0 * f0 + ps0;
        l1 = l1 * f1 + ps1;
#pragma unroll
        for (int dn = 0; dn < 4; dn++) {
            Oa[dn][0] *= f0; Oa[dn][1] *= f0;
            Oa[dn][2] *= f1; Oa[dn][3] *= f1;
        }

#pragma unroll
        for (int t2 = 0; t2 < 8; t2++) {
            uint32_t ph[4], pl[4];
            hilo2(s[2 * t2][0],     s[2 * t2][1],     ph[0], pl[0]);
            hilo2(s[2 * t2][2],     s[2 * t2][3],     ph[1], pl[1]);
            hilo2(s[2 * t2 + 1][0], s[2 * t2 + 1][1], ph[2], pl[2]);
            hilo2(s[2 * t2 + 1][2], s[2 * t2 + 1][3], ph[3], pl[3]);
#pragma unroll
            for (int dh = 0; dh < 2; dh++) {
                const uint32_t off = (uint32_t)(dh * 16 * 1040) +
                                     (uint32_t)((c * 128 + t2 * 16) * 2);
                uint32_t vb[4], vl[4];
                ldsm4(aVh0 + off, vb[0], vb[1], vb[2], vb[3]);
                ldsm4(aVl0 + off, vl[0], vl[1], vl[2], vl[3]);
#pragma unroll
                for (int od = 0; od < 2; od++) {
                    const int dn = dh * 2 + od;
                    mma_bf16(Oa[dn], ph, vb[od], vb[od + 2]);
                    mma_bf16(Oa[dn], ph, vl[od], vl[od + 2]);
                    mma_bf16(Oa[dn], pl, vb[od], vb[od + 2]);
                }
            }
        }
    }

    const float r0 = 1.f / l0, r1 = 1.f / l1;
    const int row = qc * 128 + warp * 16 + (lane >> 2);
    const int cb = 2 * (lane & 3);
    __nv_bfloat16* Oh = Osp;
    __nv_bfloat16* Ol = Osp + (size_t)NSROW * 256;
    const size_t ob = (size_t)(b * 512 + row) * 256 + h * 32 + cb;
#pragma unroll
    for (int dn = 0; dn < 4; dn++) {
        uint32_t h0, lo0, h1, lo1;
        hilo2(Oa[dn][0] * r0, Oa[dn][1] * r0, h0, lo0);
        hilo2(Oa[dn][2] * r1, Oa[dn][3] * r1, h1, lo1);
        *(uint32_t*)(Oh + ob + dn * 8)           = h0;
        *(uint32_t*)(Ol + ob + dn * 8)           = lo0;
        *(uint32_t*)(Oh + ob + 8 * 256 + dn * 8) = h1;
        *(uint32_t*)(Ol + ob + 8 * 256 + dn * 8) = lo1;
    }
}

// ---------------------------------------------------------------------------
// LayerNorm; optional second output written as split bf16 planes.
// ---------------------------------------------------------------------------
__global__ void __launch_bounds__(256)
ln_kernel(const float* __restrict__ A, const float* __restrict__ R,
          const float* __restrict__ g, const float* __restrict__ bb,
          float* __restrict__ out, int hasRes,
          __nv_bfloat16* __restrict__ out2, int stride2)
{
    __shared__ float s1[8], s2[8];
    const int t = threadIdx.x;
    const size_t row = blockIdx.x;
    float v = A[row * 256 + t];
    if (hasRes) v += R[row * 256 + t];
    float x = v, x2 = v * v;
    const int lane = t & 31, w = t >> 5;
#pragma unroll
    for (int o = 16; o; o >>= 1) {
        x  += __shfl_xor_sync(0xffffffffu, x, o);
        x2 += __shfl_xor_sync(0xffffffffu, x2, o);
    }
    if (lane == 0) { s1[w] = x; s2[w] = x2; }
    __syncthreads();
    if (t == 0) {
        float a = 0.f, c = 0.f;
        for (int i = 0; i < 8; i++) { a += s1[i]; c += s2[i]; }
        s1[0] = a * (1.f / 256.f);
        s2[0] = c * (1.f / 256.f);
    }
    __syncthreads();
    float m = s1[0];
    float var = s2[0] - m * m;
    float res = (v - m) * rsqrtf(var + 1e-5f) * g[t] + bb[t];
    out[row * 256 + t] = res;
    if (out2) {
        const size_t PL = (size_t)gridDim.x * stride2;
        const size_t o = row * stride2 + t;
        __nv_bfloat16 hh = __float2bfloat16(res);
        out2[o]      = hh;
        out2[PL + o] = __float2bfloat16(res - __bfloat162float(hh));
    }
}

// ---------------------------------------------------------------------------
// Launch (fork-join; one-time stream/event creation to stay allocation-clean)
// ---------------------------------------------------------------------------
static float* symf(const void* s) { void* p = nullptr; cudaGetSymbolAddress(&p, s); return (float*)p; }
static __nv_bfloat16* symb(const void* s) { void* p = nullptr; cudaGetSymbolAddress(&p, s); return (__nv_bfloat16*)p; }

extern "C" void kernel_launch(void* const* d_in, const int* in_sizes, int n_in,
                              void* d_out, int out_size)
{
    const float* X    = (const float*)d_in[0];
    const float* S    = (const float*)d_in[1];
    const float* Wg   = (const float*)d_in[2];
    const float* Wk   = (const float*)d_in[3];
    const float* Wm1  = (const float*)d_in[4];
    const float* bm1  = (const float*)d_in[5];
    const float* Wm2  = (const float*)d_in[6];
    const float* bm2  = (const float*)d_in[7];
    const float* Wgt1 = (const float*)d_in[8];
    const float* bgt1 = (const float*)d_in[9];
    const float* Wgt2 = (const float*)d_in[10];
    const float* bgt2 = (const float*)d_in[11];
    const float* Wqkv = (const float*)d_in[12];
    const float* bqkv = (const float*)d_in[13];
    const float* Wo   = (const float*)d_in[14];
    const float* bo   = (const float*)d_in[15];
    const float* alng = (const float*)d_in[16];
    const float* alnb = (const float*)d_in[17];
    const float* Wu1  = (const float*)d_in[18];
    const float* bu1  = (const float*)d_in[19];
    const float* Wu2  = (const float*)d_in[20];
    const float* bu2  = (const float*)d_in[21];
    const float* lng  = (const float*)d_in[22];
    const float* lnb  = (const float*)d_in[23];
    float* out = (float*)d_out;

    __nv_bfloat16* Xsp    = symb(g_Xsp);
    __nv_bfloat16* Ssp    = symb(g_Ssp);
    __nv_bfloat16* H1sp   = symb(g_H1sp);
    __nv_bfloat16* qkvsp  = symb(g_qkvsp);
    __nv_bfloat16* attnsp = symb(g_attnsp);
    __nv_bfloat16* catsp  = symb(g_catsp);
    __nv_bfloat16* Usp    = symb(g_Usp);
    __nv_bfloat16* Wm1t   = symb(g_Wm1t);
    __nv_bfloat16* Wm2t   = symb(g_Wm2t);
    __nv_bfloat16* Wgt1t  = symb(g_Wgt1t);
    __nv_bfloat16* Wqkvt  = symb(g_Wqkvt);
    __nv_bfloat16* Wot    = symb(g_Wot);
    __nv_bfloat16* Wu1t   = symb(g_Wu1t);
    __nv_bfloat16* Wu2t   = symb(g_Wu2t);
    float* msg  = symf(g_msg);
    float* T1   = symf(g_T1);
    float* gate = symf(g_gate);
    int*   idx  = (int*)[](){ void* p=nullptr; cudaGetSymbolAddress(&p, g_idx); return p; }();
    float* oprj = symf(g_oproj);
    float* S1   = symf(g_S1);
    float* S2   = symf(g_S2);

    static cudaStream_t s2 = nullptr, s3 = nullptr;
    static cudaEvent_t e0 = nullptr, eG = nullptr, eA = nullptr;
    if (s2 == nullptr) {
        cudaStreamCreateWithFlags(&s2, cudaStreamNonBlocking);
        cudaStreamCreateWithFlags(&s3, cudaStreamNonBlocking);
        cudaEventCreateWithFlags(&e0, cudaEventDisableTiming);
        cudaEventCreateWithFlags(&eG, cudaEventDisableTiming);
        cudaEventCreateWithFlags(&eA, cudaEventDisableTiming);
        cudaFuncSetAttribute(attn_tc, cudaFuncAttributeMaxDynamicSharedMemorySize, ATTN_SMEM);
        cudaFuncSetAttribute(route_kernel, cudaFuncAttributeMaxDynamicSharedMemorySize, ROUTE_SMEM);
        cudaFuncSetAttribute(bf3gemm<1,0,1>, cudaFuncAttributeMaxDynamicSharedMemorySize, GEMM_SMEM);
        cudaFuncSetAttribute(bf3gemm<1,0,0>, cudaFuncAttributeMaxDynamicSharedMemorySize, GEMM_SMEM);
        cudaFuncSetAttribute(bf3gemm<0,0,0>, cudaFuncAttributeMaxDynamicSharedMemorySize, GEMM_SMEM);
        cudaFuncSetAttribute(bf3gemm<0,0,1>, cudaFuncAttributeMaxDynamicSharedMemorySize, GEMM_SMEM);
        cudaFuncSetAttribute(bf3gemm<0,1,0>, cudaFuncAttributeMaxDynamicSharedMemorySize, GEMM_SMEM);
    }

    // pre-fork: split X (needed by main Wm1 and s2 Wgt1)
    fsplit<<<4096, 256>>>(X, Xsp, (size_t)NTOK * 256);

    cudaEventRecord(e0, (cudaStream_t)0);
    cudaStreamWaitEvent(s2, e0, 0);
    cudaStreamWaitEvent(s3, e0, 0);

    // s2: routing + gate branch; also prepares tail weights
    route_kernel<<<NTOK / 32, 256, ROUTE_SMEM, s2>>>(X, Wg, Wk, idx);
    wsplit<<<dim3(8, 8),  dim3(32, 8), 0, s2>>>(Wgt1, Wgt1t, 256, 256);
    bf3gemm<1,0,0><<<dim3(2, 256), 256, GEMM_SMEM, s2>>>(NTOK, 256, 256, Xsp, Wgt1t, bgt1, nullptr, T1);
    gate_kernel<<<NTOK / 8, 256, 0, s2>>>(T1, Wgt2, bgt2, gate);
    wsplit<<<dim3(16, 16), dim3(32, 8), 0, s2>>>(Wu1, Wu1t, 512, 512);
    wsplit<<<dim3(8, 16),  dim3(32, 8), 0, s2>>>(Wu2, Wu2t, 512, 256);
    cudaEventRecord(eG, s2);

    // s3: slot-attention branch
    fsplit<<<512, 256, 0, s3>>>(S, Ssp, (size_t)NSROW * 256);
    wsplit<<<dim3(24, 8), dim3(32, 8), 0, s3>>>(Wqkv, Wqkvt, 256, 768);
    wsplit<<<dim3(8, 8),  dim3(32, 8), 0, s3>>>(Wo, Wot, 256, 256);
    bf3gemm<0,0,1><<<dim3(6, 32), 256, GEMM_SMEM, s3>>>(NSROW, 768, 256, Ssp, Wqkvt, bqkv, nullptr, qkvsp);
    attn_tc<<<dim3(Bq * Hq, 4), 256, ATTN_SMEM, s3>>>(qkvsp, attnsp);
    bf3gemm<0,0,0><<<dim3(2, 32), 256, GEMM_SMEM, s3>>>(NSROW, 256, 256, attnsp, Wot, bo, nullptr, oprj);
    ln_kernel<<<NSROW, 256, 0, s3>>>(oprj, S, alng, alnb, S1, 1, catsp, 512);
    cudaEventRecord(eA, s3);

    // main: message branch
    wsplit<<<dim3(16, 8), dim3(32, 8)>>>(Wm1, Wm1t, 256, 512);
    wsplit<<<dim3(8, 16), dim3(32, 8)>>>(Wm2, Wm2t, 512, 256);
    bf3gemm<1,0,1><<<dim3(4, 256), 256, GEMM_SMEM>>>(NTOK, 512, 256, Xsp,  Wm1t, bm1, nullptr, H1sp);
    bf3gemm<0,0,0><<<dim3(2, 256), 256, GEMM_SMEM>>>(NTOK, 256, 512, H1sp, Wm2t, bm2, nullptr, msg);

    // join: gather needs msg + gate + idx
    cudaStreamWaitEvent((cudaStream_t)0, eG, 0);
    gather_kernel<<<NSROW, 256>>>(msg, gate, idx, catsp);

    // join: update MLP needs cat (left half from s3) + S1
    cudaStreamWaitEvent((cudaStream_t)0, eA, 0);
    bf3gemm<1,0,1><<<dim3(4, 32), 256, GEMM_SMEM>>>(NSROW, 512, 512, catsp, Wu1t, bu1, nullptr, Usp);
    bf3gemm<0,1,0><<<dim3(2, 32), 256, GEMM_SMEM>>>(NSROW, 256, 512, Usp, Wu2t, bu2, S1, S2);
    ln_kernel<<<NSROW, 256>>>(S2, nullptr, lng, lnb, out, 0, nullptr, 0);

    (void)in_sizes; (void)n_in; (void)out_size;
}

// round 11
// speedup vs baseline: 1.6506x; 1.6506x over previous
#include <cuda_runtime.h>
#include <cuda_bf16.h>
#include <cuda_fp16.h>
#include <cstdint>
#include <stdint.h>
#include <math.h>

// ---------------------------------------------------------------------------
// Problem constants
// ---------------------------------------------------------------------------
#define Bq   8
#define Lq   4096
#define Dq   256
#define Nslot 512
#define Hq   8
#define NTOK (Bq*Lq)       // 32768
#define NSROW (Bq*Nslot)   // 4096

// ---------------------------------------------------------------------------
// Device scratch. fp16 operand buffers; fp32 intermediates.
// ---------------------------------------------------------------------------
__device__ __half g_Xh   [NTOK * 256];
__device__ __half g_Sh   [NSROW * 256];
__device__ __half g_H1h  [NTOK * 512];
__device__ __half g_qkvh [NSROW * 768];
__device__ __half g_attnh[NSROW * 256];
__device__ __half g_cath [NSROW * 512];   // [ln1(S1) | incoming]
__device__ __half g_Uh   [NSROW * 512];
// weights, transposed to [N][K] fp16
__device__ __half g_Wm1t [512 * 256];
__device__ __half g_Wm2t [256 * 512];
__device__ __half g_Wgt1t[256 * 256];
__device__ __half g_Wqkvt[768 * 256];
__device__ __half g_Wot  [256 * 256];
__device__ __half g_Wu1t [512 * 512];
__device__ __half g_Wu2t [256 * 512];
// fp32 intermediates
__device__ float g_msg  [NTOK * 256];
__device__ float g_T1   [NTOK * 256];
__device__ float g_gate [NTOK];
__device__ int   g_idx  [NTOK];
__device__ float g_oproj[NSROW * 256];
__device__ float g_S1   [NSROW * 256];
__device__ float g_S2   [NSROW * 256];

// ---------------------------------------------------------------------------
// Helpers
// ---------------------------------------------------------------------------
__device__ __forceinline__ float gelu_exact(float x) {
    return 0.5f * x * (1.0f + erff(x * 0.70710678118654752f));
}

__device__ __forceinline__ void ldsm4(uint32_t addr, uint32_t& r0, uint32_t& r1,
                                      uint32_t& r2, uint32_t& r3) {
    asm volatile("ldmatrix.sync.aligned.m8n8.x4.shared.b16 {%0,%1,%2,%3}, [%4];"
                 : "=r"(r0), "=r"(r1), "=r"(r2), "=r"(r3) : "r"(addr));
}

__device__ __forceinline__ void mma_f16(float* c, const uint32_t* a,
                                        uint32_t b0, uint32_t b1) {
    asm volatile(
        "mma.sync.aligned.m16n8k16.row.col.f32.f16.f16.f32 "
        "{%0,%1,%2,%3}, {%4,%5,%6,%7}, {%8,%9}, {%0,%1,%2,%3};\n"
        : "+f"(c[0]), "+f"(c[1]), "+f"(c[2]), "+f"(c[3])
        : "r"(a[0]), "r"(a[1]), "r"(a[2]), "r"(a[3]), "r"(b0), "r"(b1));
}

__device__ __forceinline__ uint32_t h2pack(float a, float b) {
    __half2 h;
    h.x = __float2half_rn(a);
    h.y = __float2half_rn(b);
    return *(uint32_t*)&h;
}

__device__ __forceinline__ void cpasync16(uint32_t dst, const void* src) {
    asm volatile("cp.async.cg.shared.global [%0], [%1], 16;"
                 :: "r"(dst), "l"(src));
}
__device__ __forceinline__ void cpcommit() {
    asm volatile("cp.async.commit_group;" ::: "memory");
}

// ---------------------------------------------------------------------------
// Elementwise fp32 -> fp16.
// ---------------------------------------------------------------------------
__global__ void __launch_bounds__(256)
fcvt(const float* __restrict__ s, __half* __restrict__ d, size_t n)
{
    size_t i = ((size_t)blockIdx.x * 256 + threadIdx.x) * 8;
    if (i >= n) return;
    float4 a = *(const float4*)(s + i);
    float4 b = *(const float4*)(s + i + 4);
    float f[8] = {a.x, a.y, a.z, a.w, b.x, b.y, b.z, b.w};
    union { __half hh[8]; uint4 u; } u;
#pragma unroll
    for (int j = 0; j < 8; j++) u.hh[j] = __float2half_rn(f[j]);
    *(uint4*)(d + i) = u.u;
}

// ---------------------------------------------------------------------------
// Weight transpose: W[K][N] fp32 -> D[N][K] fp16.
// ---------------------------------------------------------------------------
__global__ void __launch_bounds__(256)
wcvt(const float* __restrict__ W, __half* __restrict__ D, int K, int N)
{
    __shared__ float tile[32][33];
    const int n0 = blockIdx.x * 32, k0 = blockIdx.y * 32;
    for (int i = threadIdx.y; i < 32; i += 8)
        tile[i][threadIdx.x] = W[(size_t)(k0 + i) * N + n0 + threadIdx.x];
    __syncthreads();
    for (int i = threadIdx.y; i < 32; i += 8)
        D[(size_t)(n0 + i) * K + k0 + threadIdx.x] = __float2half_rn(tile[threadIdx.x][i]);
}

// ---------------------------------------------------------------------------
// fp16 GEMM: C = epi(A(MxK) @ B(NxK)^T + bias [+Res]).
// 256 threads, 8 warps (32x64 warp tile), CTA 128x128, BK=32,
// 3-stage cp.async, 2 CTAs/SM.
// Stage (20480B): A@0 (128 rows x 80B), B@10240.
// ---------------------------------------------------------------------------
#define HSTAGE 20480
#define GEMM_SMEM (3 * HSTAGE)   // 61440

__device__ __forceinline__ void hload(
    uint32_t st, const __half* A, const __half* B, int Kd, int k0, int tid)
{
    const int r = tid >> 1, c0 = (tid & 1) * 2;
#pragma unroll
    for (int i = 0; i < 2; i++) {
        const int c = c0 + i;
        const uint32_t d = st + (uint32_t)(r * 80 + c * 16);
        const size_t g = (size_t)r * Kd + k0 + c * 8;
        cpasync16(d,         A + g);
        cpasync16(d + 10240, B + g);
    }
}

template<int ACT, int HAS_RES, int OUT_HALF>
__global__ void __launch_bounds__(256, 2)
hgemm(int M, int Nd, int Kd,
      const __half* __restrict__ A, const __half* __restrict__ B,
      const float* __restrict__ bias, const float* __restrict__ Res,
      void* __restrict__ Cout)
{
    extern __shared__ char smem[];
    const uint32_t sb = (uint32_t)__cvta_generic_to_shared(smem);

    const int tid = threadIdx.x, lane = tid & 31, warp = tid >> 5;
    const int wm = (warp & 3) * 32;     // 4 row-warps
    const int wn = (warp >> 2) * 64;    // 2 col-warps
    const int br = blockIdx.y, bc = blockIdx.x;

    const __half* Ap = A + (size_t)(br * 128) * Kd;
    const __half* Bp = B + (size_t)(bc * 128) * Kd;

    float acc[2][8][4];
#pragma unroll
    for (int i = 0; i < 2; i++)
#pragma unroll
        for (int j = 0; j < 8; j++)
#pragma unroll
            for (int q = 0; q < 4; q++) acc[i][j][q] = 0.f;

    const int lr = lane & 15;
    const uint32_t lkB = (uint32_t)(lane >> 4) * 16;
    const uint32_t aA = sb + (uint32_t)(wm + lr) * 80 + lkB;
    const uint32_t aB = sb + 10240 + (uint32_t)(wn + lr) * 80 + lkB;
    const uint32_t HOP = 16 * 80;

    const int nIter = Kd >> 5;

    hload(sb,          Ap, Bp, Kd, 0,  tid); cpcommit();
    hload(sb + HSTAGE, Ap, Bp, Kd, 32, tid); cpcommit();

    for (int it = 0; it < nIter; it++) {
        asm volatile("cp.async.wait_group 1;" ::: "memory");
        __syncthreads();

        if (it + 2 < nIter)
            hload(sb + (uint32_t)((it + 2) % 3) * HSTAGE, Ap, Bp, Kd, (it + 2) * 32, tid);
        cpcommit();

        const uint32_t po = (uint32_t)(it % 3) * HSTAGE;
#pragma unroll
        for (int ks = 0; ks < 2; ks++) {
            const uint32_t ko = po + ks * 32;
            uint32_t fa[2][4], fb[4][4];
#pragma unroll
            for (int i = 0; i < 2; i++)
                ldsm4(aA + i * HOP + ko, fa[i][0], fa[i][1], fa[i][2], fa[i][3]);
#pragma unroll
            for (int j = 0; j < 4; j++)
                ldsm4(aB + j * HOP + ko, fb[j][0], fb[j][1], fb[j][2], fb[j][3]);
#pragma unroll
            for (int i = 0; i < 2; i++)
#pragma unroll
                for (int j = 0; j < 4; j++)
#pragma unroll
                    for (int od = 0; od < 2; od++)
                        mma_f16(acc[i][j * 2 + od], fa[i], fb[j][od], fb[j][od + 2]);
        }
    }

    // epilogue
    const int er = lane >> 2;
    const int ec = (lane & 3) * 2;
#pragma unroll
    for (int i = 0; i < 2; i++) {
        const int row0 = br * 128 + wm + i * 16 + er;
#pragma unroll
        for (int j8 = 0; j8 < 8; j8++) {
            const int col = bc * 128 + wn + j8 * 8 + ec;
            const float b0 = bias[col], b1 = bias[col + 1];
            float v0 = acc[i][j8][0] + b0, v1 = acc[i][j8][1] + b1;
            float v2 = acc[i][j8][2] + b0, v3 = acc[i][j8][3] + b1;
            if (ACT) { v0 = gelu_exact(v0); v1 = gelu_exact(v1);
                       v2 = gelu_exact(v2); v3 = gelu_exact(v3); }
            const size_t o0 = (size_t)row0 * Nd + col;
            const size_t o1 = (size_t)(row0 + 8) * Nd + col;
            if (HAS_RES) {
                v0 += Res[o0]; v1 += Res[o0 + 1];
                v2 += Res[o1]; v3 += Res[o1 + 1];
            }
            if (OUT_HALF) {
                __half* C = (__half*)Cout;
                *(uint32_t*)(C + o0) = h2pack(v0, v1);
                *(uint32_t*)(C + o1) = h2pack(v2, v3);
            } else {
                float* C = (float*)Cout;
                float2 w0; w0.x = v0; w0.y = v1;
                float2 w1; w1.x = v2; w1.y = v3;
                *(float2*)&C[o0] = w0;
                *(float2*)&C[o1] = w1;
            }
        }
    }
}

// ---------------------------------------------------------------------------
// Routing with smem-cached weights (fp32, exact; validated round 5).
// ---------------------------------------------------------------------------
#define ROUTE_SMEM ((256*64 + 256*8 + 32*256) * 4)
__global__ void __launch_bounds__(256)
route_kernel(const float* __restrict__ X, const float* __restrict__ Wg,
             const float* __restrict__ Wk, int* __restrict__ idx)
{
    extern __shared__ float rsm[];
    float* sWg = rsm;
    float* sWk = rsm + 256 * 64;
    float* sX  = rsm + 256 * 64 + 256 * 8;

    const int t = threadIdx.x, lane = t & 31, w = t >> 5;
    const int tok0 = blockIdx.x * 32;

    for (int i = t; i < 256 * 64 / 4; i += 256)
        *(float4*)&sWg[i * 4] = *(const float4*)&Wg[i * 4];
    for (int i = t; i < 256 * 8 / 4; i += 256)
        *(float4*)&sWk[i * 4] = *(const float4*)&Wk[i * 4];
    for (int i = t; i < 32 * 256 / 4; i += 256)
        *(float4*)&sX[i * 4] = *(const float4*)&X[(size_t)tok0 * 256 + i * 4];
    __syncthreads();

    for (int r = 0; r < 4; r++) {
        const int tk = w * 4 + r;
        const float* x = &sX[tk * 256];
        float a0 = 0.f, a1 = 0.f, ak = 0.f;
        const int kl = lane & 7;
#pragma unroll 4
        for (int k = 0; k < 256; k++) {
            const float xv = x[k];
            a0 = fmaf(xv, sWg[k * 64 + lane], a0);
            a1 = fmaf(xv, sWg[k * 64 + lane + 32], a1);
            ak = fmaf(xv, sWk[k * 8 + kl], ak);
        }
        float bv = a0; int bi = lane;
        if (a1 > bv) { bv = a1; bi = lane + 32; }
#pragma unroll
        for (int o = 16; o; o >>= 1) {
            float ov = __shfl_xor_sync(0xffffffffu, bv, o);
            int   oi = __shfl_xor_sync(0xffffffffu, bi, o);
            if (ov > bv || (ov == bv && oi < bi)) { bv = ov; bi = oi; }
        }
        float kv = ak; int ki = kl;
#pragma unroll
        for (int o = 4; o; o >>= 1) {
            float ov = __shfl_xor_sync(0xffffffffu, kv, o);
            int   oi = __shfl_xor_sync(0xffffffffu, ki, o);
            if (ov > kv || (ov == kv && oi < ki)) { kv = ov; ki = oi; }
        }
        if (lane == 0) idx[tok0 + tk] = bi * 8 + ki;
    }
}

// ---------------------------------------------------------------------------
// gate = sigmoid(T1 . Wgt2 + bgt2)
// ---------------------------------------------------------------------------
__global__ void __launch_bounds__(256)
gate_kernel(const float* __restrict__ T1, const float* __restrict__ Wgt2,
            const float* __restrict__ bgt2, float* __restrict__ gate)
{
    const int warp = threadIdx.x >> 5, lane = threadIdx.x & 31;
    const int tok = blockIdx.x * 8 + warp;
    const float* r = T1 + (size_t)tok * 256;
    float s = 0.f;
#pragma unroll
    for (int i = 0; i < 8; i++) s = fmaf(r[lane + 32 * i], Wgt2[lane + 32 * i], s);
#pragma unroll
    for (int o = 16; o; o >>= 1) s += __shfl_xor_sync(0xffffffffu, s, o);
    if (lane == 0) gate[tok] = 1.f / (1.f + expf(-(s + bgt2[0])));
}

// ---------------------------------------------------------------------------
// incoming -> cat[:,256:512] (fp16). Ballot scan (validated round 4).
// ---------------------------------------------------------------------------
__global__ void __launch_bounds__(256)
gather_kernel(const float* __restrict__ msg, const float* __restrict__ gate,
              const int* __restrict__ idx, __half* __restrict__ cat)
{
    __shared__ float part[8][256];
    const int t = threadIdx.x, lane = t & 31, w = t >> 5;
    const int b = blockIdx.x >> 9;
    const int n = blockIdx.x & 511;
    const int base0 = b * 4096 + w * 512;

    float acc[8];
#pragma unroll
    for (int e = 0; e < 8; e++) acc[e] = 0.f;

    for (int s = 0; s < 16; s++) {
        const int l = base0 + s * 32 + lane;
        const int iv = idx[l];
        const float gv = gate[l];
        unsigned m = __ballot_sync(0xffffffffu, iv == n);
        while (m) {
            const int j = __ffs(m) - 1;
            m &= m - 1;
            const float g = __shfl_sync(0xffffffffu, gv, j);
            const float* row = msg + (size_t)(base0 + s * 32 + j) * 256;
#pragma unroll
            for (int e = 0; e < 8; e++)
                acc[e] = fmaf(g, row[e * 32 + lane], acc[e]);
        }
    }
#pragma unroll
    for (int e = 0; e < 8; e++) part[w][e * 32 + lane] = acc[e];
    __syncthreads();

    float s = 0.f;
#pragma unroll
    for (int w2 = 0; w2 < 8; w2++) s += part[w2][t];
    cat[(size_t)blockIdx.x * 512 + 256 + t] = __float2half_rn(s);
}

// ---------------------------------------------------------------------------
// fp16 tensor-core flash attention. Block = (b,h,128-q-chunk), 8 warps.
// smem (fp16): Q[128][40] @0, K[512][40] @5120, V^T[32][520] @25600.
// ---------------------------------------------------------------------------
#define ATTN_SMEM 84480
__global__ void __launch_bounds__(256, 1)
attn_tc(const __half* __restrict__ qkvh, __half* __restrict__ Oh)
{
    extern __shared__ __half abuf[];
    __half* sQ = abuf;
    __half* sK = abuf + 5120;
    __half* sV = abuf + 25600;

    const int b = blockIdx.x >> 3, h = blockIdx.x & 7;
    const int qc = blockIdx.y;
    const int tid = threadIdx.x, lane = tid & 31, warp = tid >> 5;
    const float scale = 0.17677669529663687f;

    for (int i = tid; i < 128 * 32; i += 256) {
        int q = i >> 5, d = i & 31;
        sQ[q * 40 + d] = qkvh[(size_t)(b * 512 + qc * 128 + q) * 768 + h * 32 + d];
    }
    for (int i = tid; i < 512 * 32; i += 256) {
        int n = i >> 5, d = i & 31;
        size_t offk = (size_t)(b * 512 + n) * 768 + 256 + h * 32 + d;
        sK[n * 40 + d]  = qkvh[offk];
        sV[d * 520 + n] = qkvh[offk + 256];
    }
    __syncthreads();

    const int lr = lane & 15;
    const int lkB = (lane >> 4) * 16;

    uint32_t qf[2][4];
    {
        uint32_t a0 = (uint32_t)__cvta_generic_to_shared(&sQ[(warp * 16 + lr) * 40]) + lkB;
        ldsm4(a0,      qf[0][0], qf[0][1], qf[0][2], qf[0][3]);
        ldsm4(a0 + 32, qf[1][0], qf[1][1], qf[1][2], qf[1][3]);
    }
    const uint32_t aK0 = (uint32_t)__cvta_generic_to_shared(&sK[lr * 40]) + lkB;
    const uint32_t aV0 = (uint32_t)__cvta_generic_to_shared(&sV[lr * 520]) + lkB;

    float m0 = -1e30f, m1 = -1e30f, l0 = 0.f, l1 = 0.f;
    float Oa[4][4];
#pragma unroll
    for (int i = 0; i < 4; i++)
#pragma unroll
        for (int j = 0; j < 4; j++) Oa[i][j] = 0.f;

    for (int c = 0; c < 4; c++) {
        float s[16][4];
#pragma unroll
        for (int jn = 0; jn < 16; jn++)
#pragma unroll
            for (int q = 0; q < 4; q++) s[jn][q] = 0.f;

#pragma unroll
        for (int ks = 0; ks < 2; ks++) {
#pragma unroll
            for (int jq = 0; jq < 8; jq++) {
                const uint32_t off = (uint32_t)((c * 128 + jq * 16) * 80) + ks * 32;
                uint32_t kb[4];
                ldsm4(aK0 + off, kb[0], kb[1], kb[2], kb[3]);
#pragma unroll
                for (int od = 0; od < 2; od++)
                    mma_f16(s[jq * 2 + od], qf[ks], kb[od], kb[od + 2]);
            }
        }

#pragma unroll
        for (int jn = 0; jn < 16; jn++) {
            s[jn][0] *= scale; s[jn][1] *= scale;
            s[jn][2] *= scale; s[jn][3] *= scale;
        }

        float cm0 = -1e30f, cm1 = -1e30f;
#pragma unroll
        for (int jn = 0; jn < 16; jn++) {
            cm0 = fmaxf(cm0, fmaxf(s[jn][0], s[jn][1]));
            cm1 = fmaxf(cm1, fmaxf(s[jn][2], s[jn][3]));
        }
        cm0 = fmaxf(cm0, __shfl_xor_sync(0xffffffffu, cm0, 1));
        cm0 = fmaxf(cm0, __shfl_xor_sync(0xffffffffu, cm0, 2));
        cm1 = fmaxf(cm1, __shfl_xor_sync(0xffffffffu, cm1, 1));
        cm1 = fmaxf(cm1, __shfl_xor_sync(0xffffffffu, cm1, 2));
        const float nm0 = fmaxf(m0, cm0), nm1 = fmaxf(m1, cm1);
        const float f0 = __expf(m0 - nm0), f1 = __expf(m1 - nm1);
        m0 = nm0; m1 = nm1;
        float ps0 = 0.f, ps1 = 0.f;
#pragma unroll
        for (int jn = 0; jn < 16; jn++) {
            s[jn][0] = __expf(s[jn][0] - m0);
            s[jn][1] = __expf(s[jn][1] - m0);
            s[jn][2] = __expf(s[jn][2] - m1);
            s[jn][3] = __expf(s[jn][3] - m1);
            ps0 += s[jn][0] + s[jn][1];
            ps1 += s[jn][2] + s[jn][3];
        }
        ps0 += __shfl_xor_sync(0xffffffffu, ps0, 1);
        ps0 += __shfl_xor_sync(0xffffffffu, ps0, 2);
        ps1 += __shfl_xor_sync(0xffffffffu, ps1, 1);
        ps1 += __shfl_xor_sync(0xffffffffu, ps1, 2);
        l0 = l0 * f0 + ps0;
        l1 = l1 * f1 + ps1;
#pragma unroll
        for (int dn = 0; dn < 4; dn++) {
            Oa[dn][0] *= f0; Oa[dn][1] *= f0;
            Oa[dn][2] *= f1; Oa[dn][3] *= f1;
        }

#pragma unroll
        for (int t2 = 0; t2 < 8; t2++) {
            uint32_t ph[4];
            ph[0] = h2pack(s[2 * t2][0],     s[2 * t2][1]);
            ph[1] = h2pack(s[2 * t2][2],     s[2 * t2][3]);
            ph[2] = h2pack(s[2 * t2 + 1][0], s[2 * t2 + 1][1]);
            ph[3] = h2pack(s[2 * t2 + 1][2], s[2 * t2 + 1][3]);
#pragma unroll
            for (int dh = 0; dh < 2; dh++) {
                const uint32_t off = (uint32_t)(dh * 16 * 1040) +
                                     (uint32_t)((c * 128 + t2 * 16) * 2);
                uint32_t vb[4];
                ldsm4(aV0 + off, vb[0], vb[1], vb[2], vb[3]);
#pragma unroll
                for (int od = 0; od < 2; od++)
                    mma_f16(Oa[dh * 2 + od], ph, vb[od], vb[od + 2]);
            }
        }
    }

    const float r0 = 1.f / l0, r1 = 1.f / l1;
    const int row = qc * 128 + warp * 16 + (lane >> 2);
    const int cb = 2 * (lane & 3);
    const size_t ob = (size_t)(b * 512 + row) * 256 + h * 32 + cb;
#pragma unroll
    for (int dn = 0; dn < 4; dn++) {
        *(uint32_t*)(Oh + ob + dn * 8)           = h2pack(Oa[dn][0] * r0, Oa[dn][1] * r0);
        *(uint32_t*)(Oh + ob + 8 * 256 + dn * 8) = h2pack(Oa[dn][2] * r1, Oa[dn][3] * r1);
    }
}

// ---------------------------------------------------------------------------
// LayerNorm; optional second output as fp16.
// ---------------------------------------------------------------------------
__global__ void __launch_bounds__(256)
ln_kernel(const float* __restrict__ A, const float* __restrict__ R,
          const float* __restrict__ g, const float* __restrict__ bb,
          float* __restrict__ out, int hasRes,
          __half* __restrict__ out2, int stride2)
{
    __shared__ float s1[8], s2[8];
    const int t = threadIdx.x;
    const size_t row = blockIdx.x;
    float v = A[row * 256 + t];
    if (hasRes) v += R[row * 256 + t];
    float x = v, x2 = v * v;
    const int lane = t & 31, w = t >> 5;
#pragma unroll
    for (int o = 16; o; o >>= 1) {
        x  += __shfl_xor_sync(0xffffffffu, x, o);
        x2 += __shfl_xor_sync(0xffffffffu, x2, o);
    }
    if (lane == 0) { s1[w] = x; s2[w] = x2; }
    __syncthreads();
    if (t == 0) {
        float a = 0.f, c = 0.f;
        for (int i = 0; i < 8; i++) { a += s1[i]; c += s2[i]; }
        s1[0] = a * (1.f / 256.f);
        s2[0] = c * (1.f / 256.f);
    }
    __syncthreads();
    float m = s1[0];
    float var = s2[0] - m * m;
    float res = (v - m) * rsqrtf(var + 1e-5f) * g[t] + bb[t];
    out[row * 256 + t] = res;
    if (out2) out2[row * stride2 + t] = __float2half_rn(res);
}

// ---------------------------------------------------------------------------
// Launch (fork-join; one-time stream/event creation to stay allocation-clean)
// ---------------------------------------------------------------------------
static float* symf(const void* s) { void* p = nullptr; cudaGetSymbolAddress(&p, s); return (float*)p; }
static __half* symh(const void* s) { void* p = nullptr; cudaGetSymbolAddress(&p, s); return (__half*)p; }

extern "C" void kernel_launch(void* const* d_in, const int* in_sizes, int n_in,
                              void* d_out, int out_size)
{
    const float* X    = (const float*)d_in[0];
    const float* S    = (const float*)d_in[1];
    const float* Wg   = (const float*)d_in[2];
    const float* Wk   = (const float*)d_in[3];
    const float* Wm1  = (const float*)d_in[4];
    const float* bm1  = (const float*)d_in[5];
    const float* Wm2  = (const float*)d_in[6];
    const float* bm2  = (const float*)d_in[7];
    const float* Wgt1 = (const float*)d_in[8];
    const float* bgt1 = (const float*)d_in[9];
    const float* Wgt2 = (const float*)d_in[10];
    const float* bgt2 = (const float*)d_in[11];
    const float* Wqkv = (const float*)d_in[12];
    const float* bqkv = (const float*)d_in[13];
    const float* Wo   = (const float*)d_in[14];
    const float* bo   = (const float*)d_in[15];
    const float* alng = (const float*)d_in[16];
    const float* alnb = (const float*)d_in[17];
    const float* Wu1  = (const float*)d_in[18];
    const float* bu1  = (const float*)d_in[19];
    const float* Wu2  = (const float*)d_in[20];
    const float* bu2  = (const float*)d_in[21];
    const float* lng  = (const float*)d_in[22];
    const float* lnb  = (const float*)d_in[23];
    float* out = (float*)d_out;

    __half* Xh    = symh(g_Xh);
    __half* Sh    = symh(g_Sh);
    __half* H1h   = symh(g_H1h);
    __half* qkvh  = symh(g_qkvh);
    __half* attnh = symh(g_attnh);
    __half* cath  = symh(g_cath);
    __half* Uh    = symh(g_Uh);
    __half* Wm1t  = symh(g_Wm1t);
    __half* Wm2t  = symh(g_Wm2t);
    __half* Wgt1t = symh(g_Wgt1t);
    __half* Wqkvt = symh(g_Wqkvt);
    __half* Wot   = symh(g_Wot);
    __half* Wu1t  = symh(g_Wu1t);
    __half* Wu2t  = symh(g_Wu2t);
    float* msg  = symf(g_msg);
    float* T1   = symf(g_T1);
    float* gate = symf(g_gate);
    int*   idx  = (int*)[](){ void* p=nullptr; cudaGetSymbolAddress(&p, g_idx); return p; }();
    float* oprj = symf(g_oproj);
    float* S1   = symf(g_S1);
    float* S2   = symf(g_S2);

    static cudaStream_t s2 = nullptr, s3 = nullptr;
    static cudaEvent_t e0 = nullptr, eG = nullptr, eA = nullptr;
    if (s2 == nullptr) {
        cudaStreamCreateWithFlags(&s2, cudaStreamNonBlocking);
        cudaStreamCreateWithFlags(&s3, cudaStreamNonBlocking);
        cudaEventCreateWithFlags(&e0, cudaEventDisableTiming);
        cudaEventCreateWithFlags(&eG, cudaEventDisableTiming);
        cudaEventCreateWithFlags(&eA, cudaEventDisableTiming);
        cudaFuncSetAttribute(attn_tc, cudaFuncAttributeMaxDynamicSharedMemorySize, ATTN_SMEM);
        cudaFuncSetAttribute(route_kernel, cudaFuncAttributeMaxDynamicSharedMemorySize, ROUTE_SMEM);
        cudaFuncSetAttribute(hgemm<1,0,1>, cudaFuncAttributeMaxDynamicSharedMemorySize, GEMM_SMEM);
        cudaFuncSetAttribute(hgemm<1,0,0>, cudaFuncAttributeMaxDynamicSharedMemorySize, GEMM_SMEM);
        cudaFuncSetAttribute(hgemm<0,0,0>, cudaFuncAttributeMaxDynamicSharedMemorySize, GEMM_SMEM);
        cudaFuncSetAttribute(hgemm<0,0,1>, cudaFuncAttributeMaxDynamicSharedMemorySize, GEMM_SMEM);
        cudaFuncSetAttribute(hgemm<0,1,0>, cudaFuncAttributeMaxDynamicSharedMemorySize, GEMM_SMEM);
    }

    // pre-fork: X -> fp16 (needed by main Wm1 and s2 Wgt1)
    fcvt<<<4096, 256>>>(X, Xh, (size_t)NTOK * 256);

    cudaEventRecord(e0, (cudaStream_t)0);
    cudaStreamWaitEvent(s2, e0, 0);
    cudaStreamWaitEvent(s3, e0, 0);

    // s2: routing + gate branch; also prepares tail weights
    route_kernel<<<NTOK / 32, 256, ROUTE_SMEM, s2>>>(X, Wg, Wk, idx);
    wcvt<<<dim3(8, 8),  dim3(32, 8), 0, s2>>>(Wgt1, Wgt1t, 256, 256);
    hgemm<1,0,0><<<dim3(2, 256), 256, GEMM_SMEM, s2>>>(NTOK, 256, 256, Xh, Wgt1t, bgt1, nullptr, T1);
    gate_kernel<<<NTOK / 8, 256, 0, s2>>>(T1, Wgt2, bgt2, gate);
    wcvt<<<dim3(16, 16), dim3(32, 8), 0, s2>>>(Wu1, Wu1t, 512, 512);
    wcvt<<<dim3(8, 16),  dim3(32, 8), 0, s2>>>(Wu2, Wu2t, 512, 256);
    cudaEventRecord(eG, s2);

    // s3: slot-attention branch
    fcvt<<<512, 256, 0, s3>>>(S, Sh, (size_t)NSROW * 256);
    wcvt<<<dim3(24, 8), dim3(32, 8), 0, s3>>>(Wqkv, Wqkvt, 256, 768);
    wcvt<<<dim3(8, 8),  dim3(32, 8), 0, s3>>>(Wo, Wot, 256, 256);
    hgemm<0,0,1><<<dim3(6, 32), 256, GEMM_SMEM, s3>>>(NSROW, 768, 256, Sh, Wqkvt, bqkv, nullptr, qkvh);
    attn_tc<<<dim3(Bq * Hq, 4), 256, ATTN_SMEM, s3>>>(qkvh, attnh);
    hgemm<0,0,0><<<dim3(2, 32), 256, GEMM_SMEM, s3>>>(NSROW, 256, 256, attnh, Wot, bo, nullptr, oprj);
    ln_kernel<<<NSROW, 256, 0, s3>>>(oprj, S, alng, alnb, S1, 1, cath, 512);
    cudaEventRecord(eA, s3);

    // main: message branch
    wcvt<<<dim3(16, 8), dim3(32, 8)>>>(Wm1, Wm1t, 256, 512);
    wcvt<<<dim3(8, 16), dim3(32, 8)>>>(Wm2, Wm2t, 512, 256);
    hgemm<1,0,1><<<dim3(4, 256), 256, GEMM_SMEM>>>(NTOK, 512, 256, Xh,  Wm1t, bm1, nullptr, H1h);
    hgemm<0,0,0><<<dim3(2, 256), 256, GEMM_SMEM>>>(NTOK, 256, 512, H1h, Wm2t, bm2, nullptr, msg);

    // join: gather needs msg + gate + idx
    cudaStreamWaitEvent((cudaStream_t)0, eG, 0);
    gather_kernel<<<NSROW, 256>>>(msg, gate, idx, cath);

    // join: update MLP needs cat (left half from s3) + S1
    cudaStreamWaitEvent((cudaStream_t)0, eA, 0);
    hgemm<1,0,1><<<dim3(4, 32), 256, GEMM_SMEM>>>(NSROW, 512, 512, cath, Wu1t, bu1, nullptr, Uh);
    hgemm<0,1,0><<<dim3(2, 32), 256, GEMM_SMEM>>>(NSROW, 256, 512, Uh, Wu2t, bu2, S1, S2);
    ln_kernel<<<NSROW, 256>>>(S2, nullptr, lng, lnb, out, 0, nullptr, 0);

    (void)in_sizes; (void)n_in; (void)out_size;
}

// round 12
// speedup vs baseline: 1.7296x; 1.0478x over previous
#include <cuda_runtime.h>
#include <cuda_bf16.h>
#include <cuda_fp16.h>
#include <cstdint>
#include <stdint.h>
#include <math.h>

// ---------------------------------------------------------------------------
// Problem constants
// ---------------------------------------------------------------------------
#define Bq   8
#define Lq   4096
#define Dq   256
#define Nslot 512
#define Hq   8
#define NTOK (Bq*Lq)       // 32768
#define NSROW (Bq*Nslot)   // 4096

// ---------------------------------------------------------------------------
// Device scratch. fp16 operand buffers; fp32 intermediates.
// ---------------------------------------------------------------------------
__device__ __half g_Xh   [NTOK * 256];
__device__ __half g_Sh   [NSROW * 256];
__device__ __half g_H1h  [NTOK * 512];
__device__ __half g_msgh [NTOK * 256];
__device__ __half g_T1h  [NTOK * 256];
__device__ __half g_qkvh [NSROW * 768];
__device__ __half g_attnh[NSROW * 256];
__device__ __half g_cath [NSROW * 512];   // [ln1(S1) | incoming]
__device__ __half g_Uh   [NSROW * 512];
// weights, transposed to [N][K] fp16
__device__ __half g_Wm1t [512 * 256];
__device__ __half g_Wm2t [256 * 512];
__device__ __half g_Wgt1t[256 * 256];
__device__ __half g_Wqkvt[768 * 256];
__device__ __half g_Wot  [256 * 256];
__device__ __half g_Wu1t [512 * 512];
__device__ __half g_Wu2t [256 * 512];
// fp32 intermediates
__device__ float g_gate [NTOK];
__device__ int   g_idx  [NTOK];
__device__ float g_oproj[NSROW * 256];
__device__ float g_S1   [NSROW * 256];
__device__ float g_S2   [NSROW * 256];

// ---------------------------------------------------------------------------
// Helpers
// ---------------------------------------------------------------------------
__device__ __forceinline__ float gelu_exact(float x) {
    return 0.5f * x * (1.0f + erff(x * 0.70710678118654752f));
}

__device__ __forceinline__ void ldsm4(uint32_t addr, uint32_t& r0, uint32_t& r1,
                                      uint32_t& r2, uint32_t& r3) {
    asm volatile("ldmatrix.sync.aligned.m8n8.x4.shared.b16 {%0,%1,%2,%3}, [%4];"
                 : "=r"(r0), "=r"(r1), "=r"(r2), "=r"(r3) : "r"(addr));
}

__device__ __forceinline__ void mma_f16(float* c, const uint32_t* a,
                                        uint32_t b0, uint32_t b1) {
    asm volatile(
        "mma.sync.aligned.m16n8k16.row.col.f32.f16.f16.f32 "
        "{%0,%1,%2,%3}, {%4,%5,%6,%7}, {%8,%9}, {%0,%1,%2,%3};\n"
        : "+f"(c[0]), "+f"(c[1]), "+f"(c[2]), "+f"(c[3])
        : "r"(a[0]), "r"(a[1]), "r"(a[2]), "r"(a[3]), "r"(b0), "r"(b1));
}

__device__ __forceinline__ uint32_t h2pack(float a, float b) {
    __half2 h;
    h.x = __float2half_rn(a);
    h.y = __float2half_rn(b);
    return *(uint32_t*)&h;
}

__device__ __forceinline__ void cpasync16(uint32_t dst, const void* src) {
    asm volatile("cp.async.cg.shared.global [%0], [%1], 16;"
                 :: "r"(dst), "l"(src));
}
__device__ __forceinline__ void cpcommit() {
    asm volatile("cp.async.commit_group;" ::: "memory");
}

// ---------------------------------------------------------------------------
// Elementwise fp32 -> fp16.
// ---------------------------------------------------------------------------
__global__ void __launch_bounds__(256)
fcvt(const float* __restrict__ s, __half* __restrict__ d, size_t n)
{
    size_t i = ((size_t)blockIdx.x * 256 + threadIdx.x) * 8;
    if (i >= n) return;
    float4 a = *(const float4*)(s + i);
    float4 b = *(const float4*)(s + i + 4);
    float f[8] = {a.x, a.y, a.z, a.w, b.x, b.y, b.z, b.w};
    union { __half hh[8]; uint4 u; } u;
#pragma unroll
    for (int j = 0; j < 8; j++) u.hh[j] = __float2half_rn(f[j]);
    *(uint4*)(d + i) = u.u;
}

// ---------------------------------------------------------------------------
// Weight transpose: W[K][N] fp32 -> D[N][K] fp16.
// ---------------------------------------------------------------------------
__global__ void __launch_bounds__(256)
wcvt(const float* __restrict__ W, __half* __restrict__ D, int K, int N)
{
    __shared__ float tile[32][33];
    const int n0 = blockIdx.x * 32, k0 = blockIdx.y * 32;
    for (int i = threadIdx.y; i < 32; i += 8)
        tile[i][threadIdx.x] = W[(size_t)(k0 + i) * N + n0 + threadIdx.x];
    __syncthreads();
    for (int i = threadIdx.y; i < 32; i += 8)
        D[(size_t)(n0 + i) * K + k0 + threadIdx.x] = __float2half_rn(tile[threadIdx.x][i]);
}

// ---------------------------------------------------------------------------
// fp16 GEMM, K templated (fully unrolled pipeline, constant stage offsets).
// C = epi(A(MxKD) @ B(NxKD)^T + bias [+Res]).
// 256 threads, 8 warps (32x64 warp tile), CTA 128x128, BK=32,
// 3-stage cp.async, 2 CTAs/SM.
// Stage (20480B): A@0 (128 rows x 80B), B@10240.
// ---------------------------------------------------------------------------
#define HSTAGE 20480
#define GEMM_SMEM (3 * HSTAGE)   // 61440

template<int KD>
__device__ __forceinline__ void hload(
    uint32_t st, const __half* A, const __half* B, int k0, int tid)
{
    const int r = tid >> 1, c0 = (tid & 1) * 2;
#pragma unroll
    for (int i = 0; i < 2; i++) {
        const int c = c0 + i;
        const uint32_t d = st + (uint32_t)(r * 80 + c * 16);
        const size_t g = (size_t)r * KD + k0 + c * 8;
        cpasync16(d,         A + g);
        cpasync16(d + 10240, B + g);
    }
}

template<int ACT, int HAS_RES, int OUT_HALF, int KD>
__global__ void __launch_bounds__(256, 2)
hgemm(int M, int Nd,
      const __half* __restrict__ A, const __half* __restrict__ B,
      const float* __restrict__ bias, const float* __restrict__ Res,
      void* __restrict__ Cout)
{
    extern __shared__ char smem[];
    const uint32_t sb = (uint32_t)__cvta_generic_to_shared(smem);

    const int tid = threadIdx.x, lane = tid & 31, warp = tid >> 5;
    const int wm = (warp & 3) * 32;     // 4 row-warps
    const int wn = (warp >> 2) * 64;    // 2 col-warps
    const int br = blockIdx.y, bc = blockIdx.x;

    const __half* Ap = A + (size_t)(br * 128) * KD;
    const __half* Bp = B + (size_t)(bc * 128) * KD;

    float acc[2][8][4];
#pragma unroll
    for (int i = 0; i < 2; i++)
#pragma unroll
        for (int j = 0; j < 8; j++)
#pragma unroll
            for (int q = 0; q < 4; q++) acc[i][j][q] = 0.f;

    const int lr = lane & 15;
    const uint32_t lkB = (uint32_t)(lane >> 4) * 16;
    const uint32_t aA = sb + (uint32_t)(wm + lr) * 80 + lkB;
    const uint32_t aB = sb + 10240 + (uint32_t)(wn + lr) * 80 + lkB;
    constexpr uint32_t HOP = 16 * 80;
    constexpr int nIter = KD >> 5;

    hload<KD>(sb,          Ap, Bp, 0,  tid); cpcommit();
    hload<KD>(sb + HSTAGE, Ap, Bp, 32, tid); cpcommit();

#pragma unroll
    for (int it = 0; it < nIter; it++) {
        asm volatile("cp.async.wait_group 1;" ::: "memory");
        __syncthreads();

        if (it + 2 < nIter)
            hload<KD>(sb + (uint32_t)((it + 2) % 3) * HSTAGE, Ap, Bp, (it + 2) * 32, tid);
        cpcommit();

        const uint32_t po = (uint32_t)(it % 3) * HSTAGE;
#pragma unroll
        for (int ks = 0; ks < 2; ks++) {
            const uint32_t ko = po + ks * 32;
            uint32_t fa[2][4], fb[4][4];
#pragma unroll
            for (int i = 0; i < 2; i++)
                ldsm4(aA + i * HOP + ko, fa[i][0], fa[i][1], fa[i][2], fa[i][3]);
#pragma unroll
            for (int j = 0; j < 4; j++)
                ldsm4(aB + j * HOP + ko, fb[j][0], fb[j][1], fb[j][2], fb[j][3]);
#pragma unroll
            for (int i = 0; i < 2; i++)
#pragma unroll
                for (int j = 0; j < 4; j++)
#pragma unroll
                    for (int od = 0; od < 2; od++)
                        mma_f16(acc[i][j * 2 + od], fa[i], fb[j][od], fb[j][od + 2]);
        }
    }

    // epilogue
    const int er = lane >> 2;
    const int ec = (lane & 3) * 2;
#pragma unroll
    for (int i = 0; i < 2; i++) {
        const int row0 = br * 128 + wm + i * 16 + er;
#pragma unroll
        for (int j8 = 0; j8 < 8; j8++) {
            const int col = bc * 128 + wn + j8 * 8 + ec;
            const float b0 = bias[col], b1 = bias[col + 1];
            float v0 = acc[i][j8][0] + b0, v1 = acc[i][j8][1] + b1;
            float v2 = acc[i][j8][2] + b0, v3 = acc[i][j8][3] + b1;
            if (ACT) { v0 = gelu_exact(v0); v1 = gelu_exact(v1);
                       v2 = gelu_exact(v2); v3 = gelu_exact(v3); }
            const size_t o0 = (size_t)row0 * Nd + col;
            const size_t o1 = (size_t)(row0 + 8) * Nd + col;
            if (HAS_RES) {
                v0 += Res[o0]; v1 += Res[o0 + 1];
                v2 += Res[o1]; v3 += Res[o1 + 1];
            }
            if (OUT_HALF) {
                __half* C = (__half*)Cout;
                *(uint32_t*)(C + o0) = h2pack(v0, v1);
                *(uint32_t*)(C + o1) = h2pack(v2, v3);
            } else {
                float* C = (float*)Cout;
                float2 w0; w0.x = v0; w0.y = v1;
                float2 w1; w1.x = v2; w1.y = v3;
                *(float2*)&C[o0] = w0;
                *(float2*)&C[o1] = w1;
            }
        }
    }
}

// ---------------------------------------------------------------------------
// Routing with smem-cached weights (fp32, exact; validated round 5).
// ---------------------------------------------------------------------------
#define ROUTE_SMEM ((256*64 + 256*8 + 32*256) * 4)
__global__ void __launch_bounds__(256)
route_kernel(const float* __restrict__ X, const float* __restrict__ Wg,
             const float* __restrict__ Wk, int* __restrict__ idx)
{
    extern __shared__ float rsm[];
    float* sWg = rsm;
    float* sWk = rsm + 256 * 64;
    float* sX  = rsm + 256 * 64 + 256 * 8;

    const int t = threadIdx.x, lane = t & 31, w = t >> 5;
    const int tok0 = blockIdx.x * 32;

    for (int i = t; i < 256 * 64 / 4; i += 256)
        *(float4*)&sWg[i * 4] = *(const float4*)&Wg[i * 4];
    for (int i = t; i < 256 * 8 / 4; i += 256)
        *(float4*)&sWk[i * 4] = *(const float4*)&Wk[i * 4];
    for (int i = t; i < 32 * 256 / 4; i += 256)
        *(float4*)&sX[i * 4] = *(const float4*)&X[(size_t)tok0 * 256 + i * 4];
    __syncthreads();

    for (int r = 0; r < 4; r++) {
        const int tk = w * 4 + r;
        const float* x = &sX[tk * 256];
        float a0 = 0.f, a1 = 0.f, ak = 0.f;
        const int kl = lane & 7;
#pragma unroll 4
        for (int k = 0; k < 256; k++) {
            const float xv = x[k];
            a0 = fmaf(xv, sWg[k * 64 + lane], a0);
            a1 = fmaf(xv, sWg[k * 64 + lane + 32], a1);
            ak = fmaf(xv, sWk[k * 8 + kl], ak);
        }
        float bv = a0; int bi = lane;
        if (a1 > bv) { bv = a1; bi = lane + 32; }
#pragma unroll
        for (int o = 16; o; o >>= 1) {
            float ov = __shfl_xor_sync(0xffffffffu, bv, o);
            int   oi = __shfl_xor_sync(0xffffffffu, bi, o);
            if (ov > bv || (ov == bv && oi < bi)) { bv = ov; bi = oi; }
        }
        float kv = ak; int ki = kl;
#pragma unroll
        for (int o = 4; o; o >>= 1) {
            float ov = __shfl_xor_sync(0xffffffffu, kv, o);
            int   oi = __shfl_xor_sync(0xffffffffu, ki, o);
            if (ov > kv || (ov == kv && oi < ki)) { kv = ov; ki = oi; }
        }
        if (lane == 0) idx[tok0 + tk] = bi * 8 + ki;
    }
}

// ---------------------------------------------------------------------------
// gate = sigmoid(T1 . Wgt2 + bgt2)   (T1 in fp16)
// ---------------------------------------------------------------------------
__global__ void __launch_bounds__(256)
gate_kernel(const __half* __restrict__ T1, const float* __restrict__ Wgt2,
            const float* __restrict__ bgt2, float* __restrict__ gate)
{
    const int warp = threadIdx.x >> 5, lane = threadIdx.x & 31;
    const int tok = blockIdx.x * 8 + warp;
    const __half* r = T1 + (size_t)tok * 256;
    float s = 0.f;
#pragma unroll
    for (int i = 0; i < 8; i++)
        s = fmaf(__half2float(r[lane + 32 * i]), Wgt2[lane + 32 * i], s);
#pragma unroll
    for (int o = 16; o; o >>= 1) s += __shfl_xor_sync(0xffffffffu, s, o);
    if (lane == 0) gate[tok] = 1.f / (1.f + expf(-(s + bgt2[0])));
}

// ---------------------------------------------------------------------------
// incoming -> cat[:,256:512] (fp16). Ballot scan; msg in fp16.
// ---------------------------------------------------------------------------
__global__ void __launch_bounds__(256)
gather_kernel(const __half* __restrict__ msg, const float* __restrict__ gate,
              const int* __restrict__ idx, __half* __restrict__ cat)
{
    __shared__ float part[8][256];
    const int t = threadIdx.x, lane = t & 31, w = t >> 5;
    const int b = blockIdx.x >> 9;
    const int n = blockIdx.x & 511;
    const int base0 = b * 4096 + w * 512;

    float acc[8];
#pragma unroll
    for (int e = 0; e < 8; e++) acc[e] = 0.f;

    for (int s = 0; s < 16; s++) {
        const int l = base0 + s * 32 + lane;
        const int iv = idx[l];
        const float gv = gate[l];
        unsigned m = __ballot_sync(0xffffffffu, iv == n);
        while (m) {
            const int j = __ffs(m) - 1;
            m &= m - 1;
            const float g = __shfl_sync(0xffffffffu, gv, j);
            const __half* row = msg + (size_t)(base0 + s * 32 + j) * 256;
#pragma unroll
            for (int e = 0; e < 8; e++)
                acc[e] = fmaf(g, __half2float(row[e * 32 + lane]), acc[e]);
        }
    }
#pragma unroll
    for (int e = 0; e < 8; e++) part[w][e * 32 + lane] = acc[e];
    __syncthreads();

    float s = 0.f;
#pragma unroll
    for (int w2 = 0; w2 < 8; w2++) s += part[w2][t];
    cat[(size_t)blockIdx.x * 512 + 256 + t] = __float2half_rn(s);
}

// ---------------------------------------------------------------------------
// fp16 tensor-core flash attention (validated round 11).
// ---------------------------------------------------------------------------
#define ATTN_SMEM 84480
__global__ void __launch_bounds__(256, 1)
attn_tc(const __half* __restrict__ qkvh, __half* __restrict__ Oh)
{
    extern __shared__ __half abuf[];
    __half* sQ = abuf;
    __half* sK = abuf + 5120;
    __half* sV = abuf + 25600;

    const int b = blockIdx.x >> 3, h = blockIdx.x & 7;
    const int qc = blockIdx.y;
    const int tid = threadIdx.x, lane = tid & 31, warp = tid >> 5;
    const float scale = 0.17677669529663687f;

    for (int i = tid; i < 128 * 32; i += 256) {
        int q = i >> 5, d = i & 31;
        sQ[q * 40 + d] = qkvh[(size_t)(b * 512 + qc * 128 + q) * 768 + h * 32 + d];
    }
    for (int i = tid; i < 512 * 32; i += 256) {
        int n = i >> 5, d = i & 31;
        size_t offk = (size_t)(b * 512 + n) * 768 + 256 + h * 32 + d;
        sK[n * 40 + d]  = qkvh[offk];
        sV[d * 520 + n] = qkvh[offk + 256];
    }
    __syncthreads();

    const int lr = lane & 15;
    const int lkB = (lane >> 4) * 16;

    uint32_t qf[2][4];
    {
        uint32_t a0 = (uint32_t)__cvta_generic_to_shared(&sQ[(warp * 16 + lr) * 40]) + lkB;
        ldsm4(a0,      qf[0][0], qf[0][1], qf[0][2], qf[0][3]);
        ldsm4(a0 + 32, qf[1][0], qf[1][1], qf[1][2], qf[1][3]);
    }
    const uint32_t aK0 = (uint32_t)__cvta_generic_to_shared(&sK[lr * 40]) + lkB;
    const uint32_t aV0 = (uint32_t)__cvta_generic_to_shared(&sV[lr * 520]) + lkB;

    float m0 = -1e30f, m1 = -1e30f, l0 = 0.f, l1 = 0.f;
    float Oa[4][4];
#pragma unroll
    for (int i = 0; i < 4; i++)
#pragma unroll
        for (int j = 0; j < 4; j++) Oa[i][j] = 0.f;

    for (int c = 0; c < 4; c++) {
        float s[16][4];
#pragma unroll
        for (int jn = 0; jn < 16; jn++)
#pragma unroll
            for (int q = 0; q < 4; q++) s[jn][q] = 0.f;

#pragma unroll
        for (int ks = 0; ks < 2; ks++) {
#pragma unroll
            for (int jq = 0; jq < 8; jq++) {
                const uint32_t off = (uint32_t)((c * 128 + jq * 16) * 80) + ks * 32;
                uint32_t kb[4];
                ldsm4(aK0 + off, kb[0], kb[1], kb[2], kb[3]);
#pragma unroll
                for (int od = 0; od < 2; od++)
                    mma_f16(s[jq * 2 + od], qf[ks], kb[od], kb[od + 2]);
            }
        }

#pragma unroll
        for (int jn = 0; jn < 16; jn++) {
            s[jn][0] *= scale; s[jn][1] *= scale;
            s[jn][2] *= scale; s[jn][3] *= scale;
        }

        float cm0 = -1e30f, cm1 = -1e30f;
#pragma unroll
        for (int jn = 0; jn < 16; jn++) {
            cm0 = fmaxf(cm0, fmaxf(s[jn][0], s[jn][1]));
            cm1 = fmaxf(cm1, fmaxf(s[jn][2], s[jn][3]));
        }
        cm0 = fmaxf(cm0, __shfl_xor_sync(0xffffffffu, cm0, 1));
        cm0 = fmaxf(cm0, __shfl_xor_sync(0xffffffffu, cm0, 2));
        cm1 = fmaxf(cm1, __shfl_xor_sync(0xffffffffu, cm1, 1));
        cm1 = fmaxf(cm1, __shfl_xor_sync(0xffffffffu, cm1, 2));
        const float nm0 = fmaxf(m0, cm0), nm1 = fmaxf(m1, cm1);
        const float f0 = __expf(m0 - nm0), f1 = __expf(m1 - nm1);
        m0 = nm0; m1 = nm1;
        float ps0 = 0.f, ps1 = 0.f;
#pragma unroll
        for (int jn = 0; jn < 16; jn++) {
            s[jn][0] = __expf(s[jn][0] - m0);
            s[jn][1] = __expf(s[jn][1] - m0);
            s[jn][2] = __expf(s[jn][2] - m1);
            s[jn][3] = __expf(s[jn][3] - m1);
            ps0 += s[jn][0] + s[jn][1];
            ps1 += s[jn][2] + s[jn][3];
        }
        ps0 += __shfl_xor_sync(0xffffffffu, ps0, 1);
        ps0 += __shfl_xor_sync(0xffffffffu, ps0, 2);
        ps1 += __shfl_xor_sync(0xffffffffu, ps1, 1);
        ps1 += __shfl_xor_sync(0xffffffffu, ps1, 2);
        l0 = l0 * f0 + ps0;
        l1 = l1 * f1 + ps1;
#pragma unroll
        for (int dn = 0; dn < 4; dn++) {
            Oa[dn][0] *= f0; Oa[dn][1] *= f0;
            Oa[dn][2] *= f1; Oa[dn][3] *= f1;
        }

#pragma unroll
        for (int t2 = 0; t2 < 8; t2++) {
            uint32_t ph[4];
            ph[0] = h2pack(s[2 * t2][0],     s[2 * t2][1]);
            ph[1] = h2pack(s[2 * t2][2],     s[2 * t2][3]);
            ph[2] = h2pack(s[2 * t2 + 1][0], s[2 * t2 + 1][1]);
            ph[3] = h2pack(s[2 * t2 + 1][2], s[2 * t2 + 1][3]);
#pragma unroll
            for (int dh = 0; dh < 2; dh++) {
                const uint32_t off = (uint32_t)(dh * 16 * 1040) +
                                     (uint32_t)((c * 128 + t2 * 16) * 2);
                uint32_t vb[4];
                ldsm4(aV0 + off, vb[0], vb[1], vb[2], vb[3]);
#pragma unroll
                for (int od = 0; od < 2; od++)
                    mma_f16(Oa[dh * 2 + od], ph, vb[od], vb[od + 2]);
            }
        }
    }

    const float r0 = 1.f / l0, r1 = 1.f / l1;
    const int row = qc * 128 + warp * 16 + (lane >> 2);
    const int cb = 2 * (lane & 3);
    const size_t ob = (size_t)(b * 512 + row) * 256 + h * 32 + cb;
#pragma unroll
    for (int dn = 0; dn < 4; dn++) {
        *(uint32_t*)(Oh + ob + dn * 8)           = h2pack(Oa[dn][0] * r0, Oa[dn][1] * r0);
        *(uint32_t*)(Oh + ob + 8 * 256 + dn * 8) = h2pack(Oa[dn][2] * r1, Oa[dn][3] * r1);
    }
}

// ---------------------------------------------------------------------------
// LayerNorm; optional second output as fp16.
// ---------------------------------------------------------------------------
__global__ void __launch_bounds__(256)
ln_kernel(const float* __restrict__ A, const float* __restrict__ R,
          const float* __restrict__ g, const float* __restrict__ bb,
          float* __restrict__ out, int hasRes,
          __half* __restrict__ out2, int stride2)
{
    __shared__ float s1[8], s2[8];
    const int t = threadIdx.x;
    const size_t row = blockIdx.x;
    float v = A[row * 256 + t];
    if (hasRes) v += R[row * 256 + t];
    float x = v, x2 = v * v;
    const int lane = t & 31, w = t >> 5;
#pragma unroll
    for (int o = 16; o; o >>= 1) {
        x  += __shfl_xor_sync(0xffffffffu, x, o);
        x2 += __shfl_xor_sync(0xffffffffu, x2, o);
    }
    if (lane == 0) { s1[w] = x; s2[w] = x2; }
    __syncthreads();
    if (t == 0) {
        float a = 0.f, c = 0.f;
        for (int i = 0; i < 8; i++) { a += s1[i]; c += s2[i]; }
        s1[0] = a * (1.f / 256.f);
        s2[0] = c * (1.f / 256.f);
    }
    __syncthreads();
    float m = s1[0];
    float var = s2[0] - m * m;
    float res = (v - m) * rsqrtf(var + 1e-5f) * g[t] + bb[t];
    out[row * 256 + t] = res;
    if (out2) out2[row * stride2 + t] = __float2half_rn(res);
}

// ---------------------------------------------------------------------------
// Launch (fork-join; one-time stream/event creation to stay allocation-clean)
// ---------------------------------------------------------------------------
static float* symf(const void* s) { void* p = nullptr; cudaGetSymbolAddress(&p, s); return (float*)p; }
static __half* symh(const void* s) { void* p = nullptr; cudaGetSymbolAddress(&p, s); return (__half*)p; }

extern "C" void kernel_launch(void* const* d_in, const int* in_sizes, int n_in,
                              void* d_out, int out_size)
{
    const float* X    = (const float*)d_in[0];
    const float* S    = (const float*)d_in[1];
    const float* Wg   = (const float*)d_in[2];
    const float* Wk   = (const float*)d_in[3];
    const float* Wm1  = (const float*)d_in[4];
    const float* bm1  = (const float*)d_in[5];
    const float* Wm2  = (const float*)d_in[6];
    const float* bm2  = (const float*)d_in[7];
    const float* Wgt1 = (const float*)d_in[8];
    const float* bgt1 = (const float*)d_in[9];
    const float* Wgt2 = (const float*)d_in[10];
    const float* bgt2 = (const float*)d_in[11];
    const float* Wqkv = (const float*)d_in[12];
    const float* bqkv = (const float*)d_in[13];
    const float* Wo   = (const float*)d_in[14];
    const float* bo   = (const float*)d_in[15];
    const float* alng = (const float*)d_in[16];
    const float* alnb = (const float*)d_in[17];
    const float* Wu1  = (const float*)d_in[18];
    const float* bu1  = (const float*)d_in[19];
    const float* Wu2  = (const float*)d_in[20];
    const float* bu2  = (const float*)d_in[21];
    const float* lng  = (const float*)d_in[22];
    const float* lnb  = (const float*)d_in[23];
    float* out = (float*)d_out;

    __half* Xh    = symh(g_Xh);
    __half* Sh    = symh(g_Sh);
    __half* H1h   = symh(g_H1h);
    __half* msgh  = symh(g_msgh);
    __half* T1h   = symh(g_T1h);
    __half* qkvh  = symh(g_qkvh);
    __half* attnh = symh(g_attnh);
    __half* cath  = symh(g_cath);
    __half* Uh    = symh(g_Uh);
    __half* Wm1t  = symh(g_Wm1t);
    __half* Wm2t  = symh(g_Wm2t);
    __half* Wgt1t = symh(g_Wgt1t);
    __half* Wqkvt = symh(g_Wqkvt);
    __half* Wot   = symh(g_Wot);
    __half* Wu1t  = symh(g_Wu1t);
    __half* Wu2t  = symh(g_Wu2t);
    float* gate = symf(g_gate);
    int*   idx  = (int*)[](){ void* p=nullptr; cudaGetSymbolAddress(&p, g_idx); return p; }();
    float* oprj = symf(g_oproj);
    float* S1   = symf(g_S1);
    float* S2   = symf(g_S2);

    static cudaStream_t s2 = nullptr, s3 = nullptr;
    static cudaEvent_t e0 = nullptr, eG = nullptr, eA = nullptr;
    if (s2 == nullptr) {
        cudaStreamCreateWithFlags(&s2, cudaStreamNonBlocking);
        cudaStreamCreateWithFlags(&s3, cudaStreamNonBlocking);
        cudaEventCreateWithFlags(&e0, cudaEventDisableTiming);
        cudaEventCreateWithFlags(&eG, cudaEventDisableTiming);
        cudaEventCreateWithFlags(&eA, cudaEventDisableTiming);
        cudaFuncSetAttribute(attn_tc, cudaFuncAttributeMaxDynamicSharedMemorySize, ATTN_SMEM);
        cudaFuncSetAttribute(route_kernel, cudaFuncAttributeMaxDynamicSharedMemorySize, ROUTE_SMEM);
        cudaFuncSetAttribute(hgemm<1,0,1,256>, cudaFuncAttributeMaxDynamicSharedMemorySize, GEMM_SMEM);
        cudaFuncSetAttribute(hgemm<0,0,1,512>, cudaFuncAttributeMaxDynamicSharedMemorySize, GEMM_SMEM);
        cudaFuncSetAttribute(hgemm<0,0,1,256>, cudaFuncAttributeMaxDynamicSharedMemorySize, GEMM_SMEM);
        cudaFuncSetAttribute(hgemm<0,0,0,256>, cudaFuncAttributeMaxDynamicSharedMemorySize, GEMM_SMEM);
        cudaFuncSetAttribute(hgemm<1,0,1,512>, cudaFuncAttributeMaxDynamicSharedMemorySize, GEMM_SMEM);
        cudaFuncSetAttribute(hgemm<0,1,0,512>, cudaFuncAttributeMaxDynamicSharedMemorySize, GEMM_SMEM);
    }

    // pre-fork: X -> fp16 (needed by main Wm1 and s2 Wgt1)
    fcvt<<<4096, 256>>>(X, Xh, (size_t)NTOK * 256);

    cudaEventRecord(e0, (cudaStream_t)0);
    cudaStreamWaitEvent(s2, e0, 0);
    cudaStreamWaitEvent(s3, e0, 0);

    // s2: routing + gate branch; also prepares tail weights
    route_kernel<<<NTOK / 32, 256, ROUTE_SMEM, s2>>>(X, Wg, Wk, idx);
    wcvt<<<dim3(8, 8),  dim3(32, 8), 0, s2>>>(Wgt1, Wgt1t, 256, 256);
    hgemm<1,0,1,256><<<dim3(2, 256), 256, GEMM_SMEM, s2>>>(NTOK, 256, Xh, Wgt1t, bgt1, nullptr, T1h);
    gate_kernel<<<NTOK / 8, 256, 0, s2>>>(T1h, Wgt2, bgt2, gate);
    wcvt<<<dim3(16, 16), dim3(32, 8), 0, s2>>>(Wu1, Wu1t, 512, 512);
    wcvt<<<dim3(8, 16),  dim3(32, 8), 0, s2>>>(Wu2, Wu2t, 512, 256);
    cudaEventRecord(eG, s2);

    // s3: slot-attention branch
    fcvt<<<512, 256, 0, s3>>>(S, Sh, (size_t)NSROW * 256);
    wcvt<<<dim3(24, 8), dim3(32, 8), 0, s3>>>(Wqkv, Wqkvt, 256, 768);
    wcvt<<<dim3(8, 8),  dim3(32, 8), 0, s3>>>(Wo, Wot, 256, 256);
    hgemm<0,0,1,256><<<dim3(6, 32), 256, GEMM_SMEM, s3>>>(NSROW, 768, Sh, Wqkvt, bqkv, nullptr, qkvh);
    attn_tc<<<dim3(Bq * Hq, 4), 256, ATTN_SMEM, s3>>>(qkvh, attnh);
    hgemm<0,0,0,256><<<dim3(2, 32), 256, GEMM_SMEM, s3>>>(NSROW, 256, attnh, Wot, bo, nullptr, oprj);
    ln_kernel<<<NSROW, 256, 0, s3>>>(oprj, S, alng, alnb, S1, 1, cath, 512);
    cudaEventRecord(eA, s3);

    // main: message branch
    wcvt<<<dim3(16, 8), dim3(32, 8)>>>(Wm1, Wm1t, 256, 512);
    wcvt<<<dim3(8, 16), dim3(32, 8)>>>(Wm2, Wm2t, 512, 256);
    hgemm<1,0,1,256><<<dim3(4, 256), 256, GEMM_SMEM>>>(NTOK, 512, Xh,  Wm1t, bm1, nullptr, H1h);
    hgemm<0,0,1,512><<<dim3(2, 256), 256, GEMM_SMEM>>>(NTOK, 256, H1h, Wm2t, bm2, nullptr, msgh);

    // join: gather needs msg + gate + idx
    cudaStreamWaitEvent((cudaStream_t)0, eG, 0);
    gather_kernel<<<NSROW, 256>>>(msgh, gate, idx, cath);

    // join: update MLP needs cat (left half from s3) + S1
    cudaStreamWaitEvent((cudaStream_t)0, eA, 0);
    hgemm<1,0,1,512><<<dim3(4, 32), 256, GEMM_SMEM>>>(NSROW, 512, cath, Wu1t, bu1, nullptr, Uh);
    hgemm<0,1,0,512><<<dim3(2, 32), 256, GEMM_SMEM>>>(NSROW, 256, Uh, Wu2t, bu2, S1, S2);
    ln_kernel<<<NSROW, 256>>>(S2, nullptr, lng, lnb, out, 0, nullptr, 0);

    (void)in_sizes; (void)n_in; (void)out_size;
}

// round 13
// speedup vs baseline: 1.7330x; 1.0020x over previous
#include <cuda_runtime.h>
#include <cuda_bf16.h>
#include <cuda_fp16.h>
#include <cstdint>
#include <stdint.h>
#include <math.h>

// ---------------------------------------------------------------------------
// Problem constants
// ---------------------------------------------------------------------------
#define Bq   8
#define Lq   4096
#define Dq   256
#define Nslot 512
#define Hq   8
#define NTOK (Bq*Lq)       // 32768
#define NSROW (Bq*Nslot)   // 4096

// ---------------------------------------------------------------------------
// Device scratch. fp16 operand buffers; fp32 intermediates.
// ---------------------------------------------------------------------------
__device__ __half g_Xh    [NTOK * 256];
__device__ __half g_Sh    [NSROW * 256];
__device__ __half g_H1T1h [NTOK * 768];   // [gelu(X@Wm1+bm1) | gelu(X@Wgt1+bgt1)]
__device__ __half g_msgh  [NTOK * 256];
__device__ __half g_qkvh  [NSROW * 768];
__device__ __half g_attnh [NSROW * 256];
__device__ __half g_cath  [NSROW * 512];  // [ln1(S1) | incoming]
__device__ __half g_Uh    [NSROW * 512];
// weights, transposed to [N][K] fp16
__device__ __half g_W1cat [768 * 256];    // [Wm1t ; Wgt1t]
__device__ __half g_Wm2t  [256 * 512];
__device__ __half g_Wqkvt [768 * 256];
__device__ __half g_Wot   [256 * 256];
__device__ __half g_Wu1t  [512 * 512];
__device__ __half g_Wu2t  [256 * 512];
__device__ float  g_b1cat [768];          // [bm1 ; bgt1]
// fp32 intermediates
__device__ float g_gate [NTOK];
__device__ int   g_idx  [NTOK];
__device__ float g_oproj[NSROW * 256];
__device__ float g_S1   [NSROW * 256];
__device__ float g_S2   [NSROW * 256];

// ---------------------------------------------------------------------------
// Helpers
// ---------------------------------------------------------------------------
__device__ __forceinline__ float gelu_exact(float x) {
    return 0.5f * x * (1.0f + erff(x * 0.70710678118654752f));
}

__device__ __forceinline__ void ldsm4(uint32_t addr, uint32_t& r0, uint32_t& r1,
                                      uint32_t& r2, uint32_t& r3) {
    asm volatile("ldmatrix.sync.aligned.m8n8.x4.shared.b16 {%0,%1,%2,%3}, [%4];"
                 : "=r"(r0), "=r"(r1), "=r"(r2), "=r"(r3) : "r"(addr));
}

__device__ __forceinline__ void mma_f16(float* c, const uint32_t* a,
                                        uint32_t b0, uint32_t b1) {
    asm volatile(
        "mma.sync.aligned.m16n8k16.row.col.f32.f16.f16.f32 "
        "{%0,%1,%2,%3}, {%4,%5,%6,%7}, {%8,%9}, {%0,%1,%2,%3};\n"
        : "+f"(c[0]), "+f"(c[1]), "+f"(c[2]), "+f"(c[3])
        : "r"(a[0]), "r"(a[1]), "r"(a[2]), "r"(a[3]), "r"(b0), "r"(b1));
}

__device__ __forceinline__ uint32_t h2pack(float a, float b) {
    __half2 h;
    h.x = __float2half_rn(a);
    h.y = __float2half_rn(b);
    return *(uint32_t*)&h;
}

__device__ __forceinline__ void cpasync16(uint32_t dst, const void* src) {
    asm volatile("cp.async.cg.shared.global [%0], [%1], 16;"
                 :: "r"(dst), "l"(src));
}
__device__ __forceinline__ void cpcommit() {
    asm volatile("cp.async.commit_group;" ::: "memory");
}

// ---------------------------------------------------------------------------
// Elementwise fp32 -> fp16.
// ---------------------------------------------------------------------------
__global__ void __launch_bounds__(256)
fcvt(const float* __restrict__ s, __half* __restrict__ d, size_t n)
{
    size_t i = ((size_t)blockIdx.x * 256 + threadIdx.x) * 8;
    if (i >= n) return;
    float4 a = *(const float4*)(s + i);
    float4 b = *(const float4*)(s + i + 4);
    float f[8] = {a.x, a.y, a.z, a.w, b.x, b.y, b.z, b.w};
    union { __half hh[8]; uint4 u; } u;
#pragma unroll
    for (int j = 0; j < 8; j++) u.hh[j] = __float2half_rn(f[j]);
    *(uint4*)(d + i) = u.u;
}

// ---------------------------------------------------------------------------
// Weight transpose: W[K][N] fp32 -> D[N][K] fp16.
// ---------------------------------------------------------------------------
__global__ void __launch_bounds__(256)
wcvt(const float* __restrict__ W, __half* __restrict__ D, int K, int N)
{
    __shared__ float tile[32][33];
    const int n0 = blockIdx.x * 32, k0 = blockIdx.y * 32;
    for (int i = threadIdx.y; i < 32; i += 8)
        tile[i][threadIdx.x] = W[(size_t)(k0 + i) * N + n0 + threadIdx.x];
    __syncthreads();
    for (int i = threadIdx.y; i < 32; i += 8)
        D[(size_t)(n0 + i) * K + k0 + threadIdx.x] = __float2half_rn(tile[threadIdx.x][i]);
}

// ---------------------------------------------------------------------------
// fp16 GEMM, K templated; A row stride (lda) runtime.
// C = epi(A(M x KD, stride lda) @ B(N x KD)^T + bias [+Res]).
// 256 threads, 8 warps (32x64 warp tile), CTA 128x128, BK=32,
// 3-stage cp.async, 2 CTAs/SM.
// ---------------------------------------------------------------------------
#define HSTAGE 20480
#define GEMM_SMEM (3 * HSTAGE)   // 61440

template<int KD>
__device__ __forceinline__ void hload(
    uint32_t st, const __half* A, const __half* B, int lda, int k0, int tid)
{
    const int r = tid >> 1, c0 = (tid & 1) * 2;
#pragma unroll
    for (int i = 0; i < 2; i++) {
        const int c = c0 + i;
        const uint32_t d = st + (uint32_t)(r * 80 + c * 16);
        cpasync16(d,         A + (size_t)r * lda + k0 + c * 8);
        cpasync16(d + 10240, B + (size_t)r * KD  + k0 + c * 8);
    }
}

template<int ACT, int HAS_RES, int OUT_HALF, int KD>
__global__ void __launch_bounds__(256, 2)
hgemm(int M, int Nd, int lda,
      const __half* __restrict__ A, const __half* __restrict__ B,
      const float* __restrict__ bias, const float* __restrict__ Res,
      void* __restrict__ Cout)
{
    extern __shared__ char smem[];
    const uint32_t sb = (uint32_t)__cvta_generic_to_shared(smem);

    const int tid = threadIdx.x, lane = tid & 31, warp = tid >> 5;
    const int wm = (warp & 3) * 32;
    const int wn = (warp >> 2) * 64;
    const int br = blockIdx.y, bc = blockIdx.x;

    const __half* Ap = A + (size_t)(br * 128) * lda;
    const __half* Bp = B + (size_t)(bc * 128) * KD;

    float acc[2][8][4];
#pragma unroll
    for (int i = 0; i < 2; i++)
#pragma unroll
        for (int j = 0; j < 8; j++)
#pragma unroll
            for (int q = 0; q < 4; q++) acc[i][j][q] = 0.f;

    const int lr = lane & 15;
    const uint32_t lkB = (uint32_t)(lane >> 4) * 16;
    const uint32_t aA = sb + (uint32_t)(wm + lr) * 80 + lkB;
    const uint32_t aB = sb + 10240 + (uint32_t)(wn + lr) * 80 + lkB;
    constexpr uint32_t HOP = 16 * 80;
    constexpr int nIter = KD >> 5;

    hload<KD>(sb,          Ap, Bp, lda, 0,  tid); cpcommit();
    hload<KD>(sb + HSTAGE, Ap, Bp, lda, 32, tid); cpcommit();

#pragma unroll
    for (int it = 0; it < nIter; it++) {
        asm volatile("cp.async.wait_group 1;" ::: "memory");
        __syncthreads();

        if (it + 2 < nIter)
            hload<KD>(sb + (uint32_t)((it + 2) % 3) * HSTAGE, Ap, Bp, lda, (it + 2) * 32, tid);
        cpcommit();

        const uint32_t po = (uint32_t)(it % 3) * HSTAGE;
#pragma unroll
        for (int ks = 0; ks < 2; ks++) {
            const uint32_t ko = po + ks * 32;
            uint32_t fa[2][4], fb[4][4];
#pragma unroll
            for (int i = 0; i < 2; i++)
                ldsm4(aA + i * HOP + ko, fa[i][0], fa[i][1], fa[i][2], fa[i][3]);
#pragma unroll
            for (int j = 0; j < 4; j++)
                ldsm4(aB + j * HOP + ko, fb[j][0], fb[j][1], fb[j][2], fb[j][3]);
#pragma unroll
            for (int i = 0; i < 2; i++)
#pragma unroll
                for (int j = 0; j < 4; j++)
#pragma unroll
                    for (int od = 0; od < 2; od++)
                        mma_f16(acc[i][j * 2 + od], fa[i], fb[j][od], fb[j][od + 2]);
        }
    }

    // epilogue
    const int er = lane >> 2;
    const int ec = (lane & 3) * 2;
#pragma unroll
    for (int i = 0; i < 2; i++) {
        const int row0 = br * 128 + wm + i * 16 + er;
#pragma unroll
        for (int j8 = 0; j8 < 8; j8++) {
            const int col = bc * 128 + wn + j8 * 8 + ec;
            const float b0 = bias[col], b1 = bias[col + 1];
            float v0 = acc[i][j8][0] + b0, v1 = acc[i][j8][1] + b1;
            float v2 = acc[i][j8][2] + b0, v3 = acc[i][j8][3] + b1;
            if (ACT) { v0 = gelu_exact(v0); v1 = gelu_exact(v1);
                       v2 = gelu_exact(v2); v3 = gelu_exact(v3); }
            const size_t o0 = (size_t)row0 * Nd + col;
            const size_t o1 = (size_t)(row0 + 8) * Nd + col;
            if (HAS_RES) {
                v0 += Res[o0]; v1 += Res[o0 + 1];
                v2 += Res[o1]; v3 += Res[o1 + 1];
            }
            if (OUT_HALF) {
                __half* C = (__half*)Cout;
                *(uint32_t*)(C + o0) = h2pack(v0, v1);
                *(uint32_t*)(C + o1) = h2pack(v2, v3);
            } else {
                float* C = (float*)Cout;
                float2 w0; w0.x = v0; w0.y = v1;
                float2 w1; w1.x = v2; w1.y = v3;
                *(float2*)&C[o0] = w0;
                *(float2*)&C[o1] = w1;
            }
        }
    }
}

// ---------------------------------------------------------------------------
// Routing with smem-cached weights (fp32, exact; validated round 5).
// ---------------------------------------------------------------------------
#define ROUTE_SMEM ((256*64 + 256*8 + 32*256) * 4)
__global__ void __launch_bounds__(256)
route_kernel(const float* __restrict__ X, const float* __restrict__ Wg,
             const float* __restrict__ Wk, int* __restrict__ idx)
{
    extern __shared__ float rsm[];
    float* sWg = rsm;
    float* sWk = rsm + 256 * 64;
    float* sX  = rsm + 256 * 64 + 256 * 8;

    const int t = threadIdx.x, lane = t & 31, w = t >> 5;
    const int tok0 = blockIdx.x * 32;

    for (int i = t; i < 256 * 64 / 4; i += 256)
        *(float4*)&sWg[i * 4] = *(const float4*)&Wg[i * 4];
    for (int i = t; i < 256 * 8 / 4; i += 256)
        *(float4*)&sWk[i * 4] = *(const float4*)&Wk[i * 4];
    for (int i = t; i < 32 * 256 / 4; i += 256)
        *(float4*)&sX[i * 4] = *(const float4*)&X[(size_t)tok0 * 256 + i * 4];
    __syncthreads();

    for (int r = 0; r < 4; r++) {
        const int tk = w * 4 + r;
        const float* x = &sX[tk * 256];
        float a0 = 0.f, a1 = 0.f, ak = 0.f;
        const int kl = lane & 7;
#pragma unroll 4
        for (int k = 0; k < 256; k++) {
            const float xv = x[k];
            a0 = fmaf(xv, sWg[k * 64 + lane], a0);
            a1 = fmaf(xv, sWg[k * 64 + lane + 32], a1);
            ak = fmaf(xv, sWk[k * 8 + kl], ak);
        }
        float bv = a0; int bi = lane;
        if (a1 > bv) { bv = a1; bi = lane + 32; }
#pragma unroll
        for (int o = 16; o; o >>= 1) {
            float ov = __shfl_xor_sync(0xffffffffu, bv, o);
            int   oi = __shfl_xor_sync(0xffffffffu, bi, o);
            if (ov > bv || (ov == bv && oi < bi)) { bv = ov; bi = oi; }
        }
        float kv = ak; int ki = kl;
#pragma unroll
        for (int o = 4; o; o >>= 1) {
            float ov = __shfl_xor_sync(0xffffffffu, kv, o);
            int   oi = __shfl_xor_sync(0xffffffffu, ki, o);
            if (ov > kv || (ov == kv && oi < ki)) { kv = ov; ki = oi; }
        }
        if (lane == 0) idx[tok0 + tk] = bi * 8 + ki;
    }
}

// ---------------------------------------------------------------------------
// gate = sigmoid(T1 . Wgt2 + bgt2)   (T1 = H1T1h slice, row stride 768)
// ---------------------------------------------------------------------------
__global__ void __launch_bounds__(256)
gate_kernel(const __half* __restrict__ T1, const float* __restrict__ Wgt2,
            const float* __restrict__ bgt2, float* __restrict__ gate)
{
    const int warp = threadIdx.x >> 5, lane = threadIdx.x & 31;
    const int tok = blockIdx.x * 8 + warp;
    const __half* r = T1 + (size_t)tok * 768 + 512;
    float s = 0.f;
#pragma unroll
    for (int i = 0; i < 8; i++)
        s = fmaf(__half2float(r[lane + 32 * i]), Wgt2[lane + 32 * i], s);
#pragma unroll
    for (int o = 16; o; o >>= 1) s += __shfl_xor_sync(0xffffffffu, s, o);
    if (lane == 0) gate[tok] = 1.f / (1.f + expf(-(s + bgt2[0])));
}

// ---------------------------------------------------------------------------
// incoming -> cat[:,256:512] (fp16). Ballot scan; msg in fp16.
// ---------------------------------------------------------------------------
__global__ void __launch_bounds__(256)
gather_kernel(const __half* __restrict__ msg, const float* __restrict__ gate,
              const int* __restrict__ idx, __half* __restrict__ cat)
{
    __shared__ float part[8][256];
    const int t = threadIdx.x, lane = t & 31, w = t >> 5;
    const int b = blockIdx.x >> 9;
    const int n = blockIdx.x & 511;
    const int base0 = b * 4096 + w * 512;

    float acc[8];
#pragma unroll
    for (int e = 0; e < 8; e++) acc[e] = 0.f;

    for (int s = 0; s < 16; s++) {
        const int l = base0 + s * 32 + lane;
        const int iv = idx[l];
        const float gv = gate[l];
        unsigned m = __ballot_sync(0xffffffffu, iv == n);
        while (m) {
            const int j = __ffs(m) - 1;
            m &= m - 1;
            const float g = __shfl_sync(0xffffffffu, gv, j);
            const __half* row = msg + (size_t)(base0 + s * 32 + j) * 256;
#pragma unroll
            for (int e = 0; e < 8; e++)
                acc[e] = fmaf(g, __half2float(row[e * 32 + lane]), acc[e]);
        }
    }
#pragma unroll
    for (int e = 0; e < 8; e++) part[w][e * 32 + lane] = acc[e];
    __syncthreads();

    float s = 0.f;
#pragma unroll
    for (int w2 = 0; w2 < 8; w2++) s += part[w2][t];
    cat[(size_t)blockIdx.x * 512 + 256 + t] = __float2half_rn(s);
}

// ---------------------------------------------------------------------------
// fp16 tensor-core flash attention; 2 CTAs/SM for MUFU/MMA overlap.
// ---------------------------------------------------------------------------
#define ATTN_SMEM 84480
__global__ void __launch_bounds__(256, 2)
attn_tc(const __half* __restrict__ qkvh, __half* __restrict__ Oh)
{
    extern __shared__ __half abuf[];
    __half* sQ = abuf;
    __half* sK = abuf + 5120;
    __half* sV = abuf + 25600;

    const int b = blockIdx.x >> 3, h = blockIdx.x & 7;
    const int qc = blockIdx.y;
    const int tid = threadIdx.x, lane = tid & 31, warp = tid >> 5;
    const float scale = 0.17677669529663687f;

    for (int i = tid; i < 128 * 32; i += 256) {
        int q = i >> 5, d = i & 31;
        sQ[q * 40 + d] = qkvh[(size_t)(b * 512 + qc * 128 + q) * 768 + h * 32 + d];
    }
    for (int i = tid; i < 512 * 32; i += 256) {
        int n = i >> 5, d = i & 31;
        size_t offk = (size_t)(b * 512 + n) * 768 + 256 + h * 32 + d;
        sK[n * 40 + d]  = qkvh[offk];
        sV[d * 520 + n] = qkvh[offk + 256];
    }
    __syncthreads();

    const int lr = lane & 15;
    const int lkB = (lane >> 4) * 16;

    uint32_t qf[2][4];
    {
        uint32_t a0 = (uint32_t)__cvta_generic_to_shared(&sQ[(warp * 16 + lr) * 40]) + lkB;
        ldsm4(a0,      qf[0][0], qf[0][1], qf[0][2], qf[0][3]);
        ldsm4(a0 + 32, qf[1][0], qf[1][1], qf[1][2], qf[1][3]);
    }
    const uint32_t aK0 = (uint32_t)__cvta_generic_to_shared(&sK[lr * 40]) + lkB;
    const uint32_t aV0 = (uint32_t)__cvta_generic_to_shared(&sV[lr * 520]) + lkB;

    float m0 = -1e30f, m1 = -1e30f, l0 = 0.f, l1 = 0.f;
    float Oa[4][4];
#pragma unroll
    for (int i = 0; i < 4; i++)
#pragma unroll
        for (int j = 0; j < 4; j++) Oa[i][j] = 0.f;

    for (int c = 0; c < 4; c++) {
        float s[16][4];
#pragma unroll
        for (int jn = 0; jn < 16; jn++)
#pragma unroll
            for (int q = 0; q < 4; q++) s[jn][q] = 0.f;

#pragma unroll
        for (int ks = 0; ks < 2; ks++) {
#pragma unroll
            for (int jq = 0; jq < 8; jq++) {
                const uint32_t off = (uint32_t)((c * 128 + jq * 16) * 80) + ks * 32;
                uint32_t kb[4];
                ldsm4(aK0 + off, kb[0], kb[1], kb[2], kb[3]);
#pragma unroll
                for (int od = 0; od < 2; od++)
                    mma_f16(s[jq * 2 + od], qf[ks], kb[od], kb[od + 2]);
            }
        }

#pragma unroll
        for (int jn = 0; jn < 16; jn++) {
            s[jn][0] *= scale; s[jn][1] *= scale;
            s[jn][2] *= scale; s[jn][3] *= scale;
        }

        float cm0 = -1e30f, cm1 = -1e30f;
#pragma unroll
        for (int jn = 0; jn < 16; jn++) {
            cm0 = fmaxf(cm0, fmaxf(s[jn][0], s[jn][1]));
            cm1 = fmaxf(cm1, fmaxf(s[jn][2], s[jn][3]));
        }
        cm0 = fmaxf(cm0, __shfl_xor_sync(0xffffffffu, cm0, 1));
        cm0 = fmaxf(cm0, __shfl_xor_sync(0xffffffffu, cm0, 2));
        cm1 = fmaxf(cm1, __shfl_xor_sync(0xffffffffu, cm1, 1));
        cm1 = fmaxf(cm1, __shfl_xor_sync(0xffffffffu, cm1, 2));
        const float nm0 = fmaxf(m0, cm0), nm1 = fmaxf(m1, cm1);
        const float f0 = __expf(m0 - nm0), f1 = __expf(m1 - nm1);
        m0 = nm0; m1 = nm1;
        float ps0 = 0.f, ps1 = 0.f;
#pragma unroll
        for (int jn = 0; jn < 16; jn++) {
            s[jn][0] = __expf(s[jn][0] - m0);
            s[jn][1] = __expf(s[jn][1] - m0);
            s[jn][2] = __expf(s[jn][2] - m1);
            s[jn][3] = __expf(s[jn][3] - m1);
            ps0 += s[jn][0] + s[jn][1];
            ps1 += s[jn][2] + s[jn][3];
        }
        ps0 += __shfl_xor_sync(0xffffffffu, ps0, 1);
        ps0 += __shfl_xor_sync(0xffffffffu, ps0, 2);
        ps1 += __shfl_xor_sync(0xffffffffu, ps1, 1);
        ps1 += __shfl_xor_sync(0xffffffffu, ps1, 2);
        l0 = l0 * f0 + ps0;
        l1 = l1 * f1 + ps1;
#pragma unroll
        for (int dn = 0; dn < 4; dn++) {
            Oa[dn][0] *= f0; Oa[dn][1] *= f0;
            Oa[dn][2] *= f1; Oa[dn][3] *= f1;
        }

#pragma unroll
        for (int t2 = 0; t2 < 8; t2++) {
            uint32_t ph[4];
            ph[0] = h2pack(s[2 * t2][0],     s[2 * t2][1]);
            ph[1] = h2pack(s[2 * t2][2],     s[2 * t2][3]);
            ph[2] = h2pack(s[2 * t2 + 1][0], s[2 * t2 + 1][1]);
            ph[3] = h2pack(s[2 * t2 + 1][2], s[2 * t2 + 1][3]);
#pragma unroll
            for (int dh = 0; dh < 2; dh++) {
                const uint32_t off = (uint32_t)(dh * 16 * 1040) +
                                     (uint32_t)((c * 128 + t2 * 16) * 2);
                uint32_t vb[4];
                ldsm4(aV0 + off, vb[0], vb[1], vb[2], vb[3]);
#pragma unroll
                for (int od = 0; od < 2; od++)
                    mma_f16(Oa[dh * 2 + od], ph, vb[od], vb[od + 2]);
            }
        }
    }

    const float r0 = 1.f / l0, r1 = 1.f / l1;
    const int row = qc * 128 + warp * 16 + (lane >> 2);
    const int cb = 2 * (lane & 3);
    const size_t ob = (size_t)(b * 512 + row) * 256 + h * 32 + cb;
#pragma unroll
    for (int dn = 0; dn < 4; dn++) {
        *(uint32_t*)(Oh + ob + dn * 8)           = h2pack(Oa[dn][0] * r0, Oa[dn][1] * r0);
        *(uint32_t*)(Oh + ob + 8 * 256 + dn * 8) = h2pack(Oa[dn][2] * r1, Oa[dn][3] * r1);
    }
}

// ---------------------------------------------------------------------------
// LayerNorm; optional second output as fp16.
// ---------------------------------------------------------------------------
__global__ void __launch_bounds__(256)
ln_kernel(const float* __restrict__ A, const float* __restrict__ R,
          const float* __restrict__ g, const float* __restrict__ bb,
          float* __restrict__ out, int hasRes,
          __half* __restrict__ out2, int stride2)
{
    __shared__ float s1[8], s2[8];
    const int t = threadIdx.x;
    const size_t row = blockIdx.x;
    float v = A[row * 256 + t];
    if (hasRes) v += R[row * 256 + t];
    float x = v, x2 = v * v;
    const int lane = t & 31, w = t >> 5;
#pragma unroll
    for (int o = 16; o; o >>= 1) {
        x  += __shfl_xor_sync(0xffffffffu, x, o);
        x2 += __shfl_xor_sync(0xffffffffu, x2, o);
    }
    if (lane == 0) { s1[w] = x; s2[w] = x2; }
    __syncthreads();
    if (t == 0) {
        float a = 0.f, c = 0.f;
        for (int i = 0; i < 8; i++) { a += s1[i]; c += s2[i]; }
        s1[0] = a * (1.f / 256.f);
        s2[0] = c * (1.f / 256.f);
    }
    __syncthreads();
    float m = s1[0];
    float var = s2[0] - m * m;
    float res = (v - m) * rsqrtf(var + 1e-5f) * g[t] + bb[t];
    out[row * 256 + t] = res;
    if (out2) out2[row * stride2 + t] = __float2half_rn(res);
}

// ---------------------------------------------------------------------------
// Launch (fork-join; one-time stream/event creation to stay allocation-clean)
// ---------------------------------------------------------------------------
static float* symf(const void* s) { void* p = nullptr; cudaGetSymbolAddress(&p, s); return (float*)p; }
static __half* symh(const void* s) { void* p = nullptr; cudaGetSymbolAddress(&p, s); return (__half*)p; }

extern "C" void kernel_launch(void* const* d_in, const int* in_sizes, int n_in,
                              void* d_out, int out_size)
{
    const float* X    = (const float*)d_in[0];
    const float* S    = (const float*)d_in[1];
    const float* Wg   = (const float*)d_in[2];
    const float* Wk   = (const float*)d_in[3];
    const float* Wm1  = (const float*)d_in[4];
    const float* bm1  = (const float*)d_in[5];
    const float* Wm2  = (const float*)d_in[6];
    const float* bm2  = (const float*)d_in[7];
    const float* Wgt1 = (const float*)d_in[8];
    const float* bgt1 = (const float*)d_in[9];
    const float* Wgt2 = (const float*)d_in[10];
    const float* bgt2 = (const float*)d_in[11];
    const float* Wqkv = (const float*)d_in[12];
    const float* bqkv = (const float*)d_in[13];
    const float* Wo   = (const float*)d_in[14];
    const float* bo   = (const float*)d_in[15];
    const float* alng = (const float*)d_in[16];
    const float* alnb = (const float*)d_in[17];
    const float* Wu1  = (const float*)d_in[18];
    const float* bu1  = (const float*)d_in[19];
    const float* Wu2  = (const float*)d_in[20];
    const float* bu2  = (const float*)d_in[21];
    const float* lng  = (const float*)d_in[22];
    const float* lnb  = (const float*)d_in[23];
    float* out = (float*)d_out;

    __half* Xh    = symh(g_Xh);
    __half* Sh    = symh(g_Sh);
    __half* H1T1h = symh(g_H1T1h);
    __half* msgh  = symh(g_msgh);
    __half* qkvh  = symh(g_qkvh);
    __half* attnh = symh(g_attnh);
    __half* cath  = symh(g_cath);
    __half* Uh    = symh(g_Uh);
    __half* W1cat = symh(g_W1cat);
    __half* Wm2t  = symh(g_Wm2t);
    __half* Wqkvt = symh(g_Wqkvt);
    __half* Wot   = symh(g_Wot);
    __half* Wu1t  = symh(g_Wu1t);
    __half* Wu2t  = symh(g_Wu2t);
    float* b1cat = symf(g_b1cat);
    float* gate = symf(g_gate);
    int*   idx  = (int*)[](){ void* p=nullptr; cudaGetSymbolAddress(&p, g_idx); return p; }();
    float* oprj = symf(g_oproj);
    float* S1   = symf(g_S1);
    float* S2   = symf(g_S2);

    static cudaStream_t s2 = nullptr, s3 = nullptr;
    static cudaEvent_t e0 = nullptr, eG = nullptr, eA = nullptr;
    if (s2 == nullptr) {
        cudaStreamCreateWithFlags(&s2, cudaStreamNonBlocking);
        cudaStreamCreateWithFlags(&s3, cudaStreamNonBlocking);
        cudaEventCreateWithFlags(&e0, cudaEventDisableTiming);
        cudaEventCreateWithFlags(&eG, cudaEventDisableTiming);
        cudaEventCreateWithFlags(&eA, cudaEventDisableTiming);
        cudaFuncSetAttribute(attn_tc, cudaFuncAttributeMaxDynamicSharedMemorySize, ATTN_SMEM);
        cudaFuncSetAttribute(route_kernel, cudaFuncAttributeMaxDynamicSharedMemorySize, ROUTE_SMEM);
        cudaFuncSetAttribute(hgemm<1,0,1,256>, cudaFuncAttributeMaxDynamicSharedMemorySize, GEMM_SMEM);
        cudaFuncSetAttribute(hgemm<0,0,1,512>, cudaFuncAttributeMaxDynamicSharedMemorySize, GEMM_SMEM);
        cudaFuncSetAttribute(hgemm<0,0,1,256>, cudaFuncAttributeMaxDynamicSharedMemorySize, GEMM_SMEM);
        cudaFuncSetAttribute(hgemm<0,0,0,256>, cudaFuncAttributeMaxDynamicSharedMemorySize, GEMM_SMEM);
        cudaFuncSetAttribute(hgemm<1,0,1,512>, cudaFuncAttributeMaxDynamicSharedMemorySize, GEMM_SMEM);
        cudaFuncSetAttribute(hgemm<0,1,0,512>, cudaFuncAttributeMaxDynamicSharedMemorySize, GEMM_SMEM);
    }

    // fork immediately — route (s2) and slot branch (s3) need no fp16 prep
    cudaEventRecord(e0, (cudaStream_t)0);
    cudaStreamWaitEvent(s2, e0, 0);
    cudaStreamWaitEvent(s3, e0, 0);

    // s2: routing + tail-weight prep
    route_kernel<<<NTOK / 32, 256, ROUTE_SMEM, s2>>>(X, Wg, Wk, idx);
    wcvt<<<dim3(16, 16), dim3(32, 8), 0, s2>>>(Wu1, Wu1t, 512, 512);
    wcvt<<<dim3(8, 16),  dim3(32, 8), 0, s2>>>(Wu2, Wu2t, 512, 256);
    cudaEventRecord(eG, s2);

    // s3: slot-attention branch
    fcvt<<<512, 256, 0, s3>>>(S, Sh, (size_t)NSROW * 256);
    wcvt<<<dim3(24, 8), dim3(32, 8), 0, s3>>>(Wqkv, Wqkvt, 256, 768);
    wcvt<<<dim3(8, 8),  dim3(32, 8), 0, s3>>>(Wo, Wot, 256, 256);
    hgemm<0,0,1,256><<<dim3(6, 32), 256, GEMM_SMEM, s3>>>(NSROW, 768, 256, Sh, Wqkvt, bqkv, nullptr, qkvh);
    attn_tc<<<dim3(Bq * Hq, 4), 256, ATTN_SMEM, s3>>>(qkvh, attnh);
    hgemm<0,0,0,256><<<dim3(2, 32), 256, GEMM_SMEM, s3>>>(NSROW, 256, 256, attnh, Wot, bo, nullptr, oprj);
    ln_kernel<<<NSROW, 256, 0, s3>>>(oprj, S, alng, alnb, S1, 1, cath, 512);
    cudaEventRecord(eA, s3);

    // main: token branch (fused Wm1|Wgt1 GEMM, then Wm2, gate, gather)
    fcvt<<<4096, 256>>>(X, Xh, (size_t)NTOK * 256);
    cudaMemcpyAsync(b1cat,       bm1,  512 * sizeof(float), cudaMemcpyDeviceToDevice, (cudaStream_t)0);
    cudaMemcpyAsync(b1cat + 512, bgt1, 256 * sizeof(float), cudaMemcpyDeviceToDevice, (cudaStream_t)0);
    wcvt<<<dim3(16, 8), dim3(32, 8)>>>(Wm1,  W1cat,             256, 512);
    wcvt<<<dim3(8, 8),  dim3(32, 8)>>>(Wgt1, W1cat + 512 * 256, 256, 256);
    wcvt<<<dim3(8, 16), dim3(32, 8)>>>(Wm2, Wm2t, 512, 256);
    hgemm<1,0,1,256><<<dim3(6, 256), 256, GEMM_SMEM>>>(NTOK, 768, 256, Xh, W1cat, b1cat, nullptr, H1T1h);
    hgemm<0,0,1,512><<<dim3(2, 256), 256, GEMM_SMEM>>>(NTOK, 256, 768, H1T1h, Wm2t, bm2, nullptr, msgh);
    gate_kernel<<<NTOK / 8, 256>>>(H1T1h, Wgt2, bgt2, gate);

    // join: gather needs msg + gate + idx (route on s2)
    cudaStreamWaitEvent((cudaStream_t)0, eG, 0);
    gather_kernel<<<NSROW, 256>>>(msgh, gate, idx, cath);

    // join: update MLP needs cat (left half from s3) + S1
    cudaStreamWaitEvent((cudaStream_t)0, eA, 0);
    hgemm<1,0,1,512><<<dim3(4, 32), 256, GEMM_SMEM>>>(NSROW, 512, 512, cath, Wu1t, bu1, nullptr, Uh);
    hgemm<0,1,0,512><<<dim3(2, 32), 256, GEMM_SMEM>>>(NSROW, 256, 512, Uh, Wu2t, bu2, S1, S2);
    ln_kernel<<<NSROW, 256>>>(S2, nullptr, lng, lnb, out, 0, nullptr, 0);

    (void)in_sizes; (void)n_in; (void)out_size;
}